// round 3
// baseline (speedup 1.0000x reference)
#include <cuda_runtime.h>
#include <math.h>

#define Bv 8
#define Cv 512
#define Tv 1024
#define Hh 8
#define KCv 64
#define TS 65   // attention smem tile stride

// Scratch (allocation-free rule: __device__ globals)
__device__ float d_Q[Bv * Cv * Tv];
__device__ float d_K[Bv * Cv * Tv];
__device__ float d_V[Bv * Cv * Tv];
__device__ float d_A[Bv * Cv * Tv];

// ---------------------------------------------------------------------------
// Batched projection GEMM: out[b,o,t] = (sum_c W[o,c] * in[b,c,t] + bias[o]) * scale
// grid: (T/64, C/64, B), block 256, 64x64 tile, BK=16, 4x4 per thread.
// ---------------------------------------------------------------------------
__global__ __launch_bounds__(256) void proj_gemm(
    const float* __restrict__ Wm, const float* __restrict__ bias,
    const float* __restrict__ in, float* __restrict__ out, float scale)
{
    __shared__ float sA[16 * 64];  // [k][o]
    __shared__ float sB[16 * 64];  // [k][t]

    const int t0 = blockIdx.x * 64;
    const int o0 = blockIdx.y * 64;
    const int b  = blockIdx.z;
    const int tid = threadIdx.x;
    const int ty = tid >> 4, tx = tid & 15;

    const int la_o = tid >> 2;        // 0..63
    const int la_c = (tid & 3) * 4;   // 0,4,8,12
    const int lb_k = tid >> 4;        // 0..15
    const int lb_t = (tid & 15) * 4;  // 0..60

    const float* inb = in + (size_t)b * Cv * Tv;

    float acc[4][4];
#pragma unroll
    for (int i = 0; i < 4; i++)
#pragma unroll
        for (int j = 0; j < 4; j++) acc[i][j] = 0.f;

    for (int c0 = 0; c0 < Cv; c0 += 16) {
        float4 wa = *reinterpret_cast<const float4*>(&Wm[(size_t)(o0 + la_o) * Cv + c0 + la_c]);
        float4 xb = *reinterpret_cast<const float4*>(&inb[(size_t)(c0 + lb_k) * Tv + t0 + lb_t]);
        __syncthreads();
        sA[(la_c + 0) * 64 + la_o] = wa.x;
        sA[(la_c + 1) * 64 + la_o] = wa.y;
        sA[(la_c + 2) * 64 + la_o] = wa.z;
        sA[(la_c + 3) * 64 + la_o] = wa.w;
        *reinterpret_cast<float4*>(&sB[lb_k * 64 + lb_t]) = xb;
        __syncthreads();
#pragma unroll
        for (int k = 0; k < 16; k++) {
            const float4 a4 = *reinterpret_cast<const float4*>(&sA[k * 64 + ty * 4]);
            const float4 b4 = *reinterpret_cast<const float4*>(&sB[k * 64 + tx * 4]);
            const float av[4] = {a4.x, a4.y, a4.z, a4.w};
            const float bv[4] = {b4.x, b4.y, b4.z, b4.w};
#pragma unroll
            for (int i = 0; i < 4; i++)
#pragma unroll
                for (int j = 0; j < 4; j++) acc[i][j] += av[i] * bv[j];
        }
    }

#pragma unroll
    for (int i = 0; i < 4; i++) {
        const int o = o0 + ty * 4 + i;
        const float bo = bias[o];
        float4 r;
        r.x = (acc[i][0] + bo) * scale;
        r.y = (acc[i][1] + bo) * scale;
        r.z = (acc[i][2] + bo) * scale;
        r.w = (acc[i][3] + bo) * scale;
        *reinterpret_cast<float4*>(&out[((size_t)b * Cv + o) * Tv + t0 + tx * 4]) = r;
    }
}

// ---------------------------------------------------------------------------
// Banded flash attention with relative-position logits/values + proximal bias.
// grid: (T/64, H, B), block 256 (16x16 threads, 4x4 micro-tiles).
// Q already pre-scaled by 1/sqrt(KC) at projection time.
// ---------------------------------------------------------------------------
__global__ __launch_bounds__(256) void attn_kernel(
    const float* __restrict__ mask, const float* __restrict__ ek,
    const float* __restrict__ ev)
{
    extern __shared__ float sm[];
    float* sQ    = sm;              // [kc][t] stride TS
    float* sK    = sQ + 64 * TS;    // [kc][s] stride TS
    float* sV    = sK + 64 * TS;    // [s][kc] stride TS
    float* sP    = sV + 64 * TS;    // [t][s]  stride TS (reused as [kc][t] at end)
    float* sEK   = sP + 64 * TS;    // [9][64]
    float* sEV   = sEK + 576;       // [9][64]
    float* sRK   = sEV + 576;       // [t][d] stride 12
    float* sBias = sRK + 64 * 12;   // [513]: -log1p(|d|), d = i-256

    const int t0 = blockIdx.x * 64;
    const int h  = blockIdx.y;
    const int b  = blockIdx.z;
    const int tid = threadIdx.x;
    const int ty = tid >> 4, tx = tid & 15;

    const size_t qbase = ((size_t)b * Cv + h * KCv) * Tv;

    // Load Q tile (q already scaled by 1/8)
    for (int i = tid; i < 4096; i += 256) {
        const int kc = i >> 6, t = i & 63;
        sQ[kc * TS + t] = d_Q[qbase + (size_t)kc * Tv + t0 + t];
    }
    for (int i = tid; i < 576; i += 256) { sEK[i] = ek[i]; sEV[i] = ev[i]; }
    for (int i = tid; i < 513; i += 256)
        sBias[i] = -log1pf(fabsf((float)(i - 256)));
    __syncthreads();

    // Per-row relative-key logits: sRK[t][d] = sum_kc qs[t][kc] * ek[d][kc]
    for (int i = tid; i < 576; i += 256) {
        const int t = i & 63, dd = i >> 6;
        float s = 0.f;
#pragma unroll 16
        for (int kc = 0; kc < 64; kc++) s += sQ[kc * TS + t] * sEK[dd * 64 + kc];
        sRK[t * 12 + dd] = s;
    }

    float m_r[4], l_r[4], acc[4][4];
#pragma unroll
    for (int i = 0; i < 4; i++) {
        m_r[i] = -1e30f; l_r[i] = 0.f;
#pragma unroll
        for (int j = 0; j < 4; j++) acc[i][j] = 0.f;
    }

    const int s_lo = max(0, t0 - 256);
    const int s_hi = min(Tv, t0 + 64 + 256);
    const size_t mbase = (size_t)b * Tv * Tv;

    for (int s0 = s_lo; s0 < s_hi; s0 += 64) {
        __syncthreads();  // protect sK/sV/sP from previous iteration readers
        for (int i = tid; i < 4096; i += 256) {
            const int kc = i >> 6, s = i & 63;
            const float kval = d_K[qbase + (size_t)kc * Tv + s0 + s];
            const float vval = d_V[qbase + (size_t)kc * Tv + s0 + s];
            sK[kc * TS + s] = kval;
            sV[s * TS + kc] = vval;
        }
        __syncthreads();

        // S = Q K^T (4x4 per thread)
        float sv[4][4];
#pragma unroll
        for (int i = 0; i < 4; i++)
#pragma unroll
            for (int j = 0; j < 4; j++) sv[i][j] = 0.f;
#pragma unroll 8
        for (int kc = 0; kc < 64; kc++) {
            float qv[4], kv[4];
#pragma unroll
            for (int i = 0; i < 4; i++) qv[i] = sQ[kc * TS + ty * 4 + i];
#pragma unroll
            for (int j = 0; j < 4; j++) kv[j] = sK[kc * TS + tx * 4 + j];
#pragma unroll
            for (int i = 0; i < 4; i++)
#pragma unroll
                for (int j = 0; j < 4; j++) sv[i][j] += qv[i] * kv[j];
        }

        // biases + band + mask
#pragma unroll
        for (int i = 0; i < 4; i++) {
            const int t = t0 + ty * 4 + i;
#pragma unroll
            for (int j = 0; j < 4; j++) {
                const int s = s0 + tx * 4 + j;
                const int d = s - t;
                float val;
                if (d >= -256 && d <= 256) {
                    val = sv[i][j] + sBias[d + 256];
                    if (d >= -4 && d <= 4) val += sRK[(ty * 4 + i) * 12 + d + 4];
                    if (mask[mbase + (size_t)t * Tv + s] == 0.f) val = -1e30f;
                } else {
                    val = -1e30f;
                }
                sv[i][j] = val;
            }
        }

        // online softmax per row (row spread over 16 lanes of a half-warp)
        float scale_r[4];
#pragma unroll
        for (int i = 0; i < 4; i++) {
            float rm = fmaxf(fmaxf(sv[i][0], sv[i][1]), fmaxf(sv[i][2], sv[i][3]));
            rm = fmaxf(rm, __shfl_xor_sync(0xffffffffu, rm, 8));
            rm = fmaxf(rm, __shfl_xor_sync(0xffffffffu, rm, 4));
            rm = fmaxf(rm, __shfl_xor_sync(0xffffffffu, rm, 2));
            rm = fmaxf(rm, __shfl_xor_sync(0xffffffffu, rm, 1));
            const float mn = fmaxf(m_r[i], rm);
            const float sc = __expf(m_r[i] - mn);
            float rs = 0.f;
#pragma unroll
            for (int j = 0; j < 4; j++) {
                const float p = __expf(sv[i][j] - mn);
                sv[i][j] = p;
                rs += p;
            }
            rs += __shfl_xor_sync(0xffffffffu, rs, 8);
            rs += __shfl_xor_sync(0xffffffffu, rs, 4);
            rs += __shfl_xor_sync(0xffffffffu, rs, 2);
            rs += __shfl_xor_sync(0xffffffffu, rs, 1);
            l_r[i] = l_r[i] * sc + rs;
            m_r[i] = mn;
            scale_r[i] = sc;
        }

        // stage P
#pragma unroll
        for (int i = 0; i < 4; i++)
#pragma unroll
            for (int j = 0; j < 4; j++)
                sP[(ty * 4 + i) * TS + tx * 4 + j] = sv[i][j];
        __syncthreads();

        // O = O*scale + P V   (4x4 per thread over (t, kc))
#pragma unroll
        for (int i = 0; i < 4; i++)
#pragma unroll
            for (int j = 0; j < 4; j++) acc[i][j] *= scale_r[i];
#pragma unroll 4
        for (int s = 0; s < 64; s++) {
            float pv[4], vv[4];
#pragma unroll
            for (int i = 0; i < 4; i++) pv[i] = sP[(ty * 4 + i) * TS + s];
#pragma unroll
            for (int j = 0; j < 4; j++) vv[j] = sV[s * TS + tx * 4 + j];
#pragma unroll
            for (int i = 0; i < 4; i++)
#pragma unroll
                for (int j = 0; j < 4; j++) acc[i][j] += pv[i] * vv[j];
        }

        // relative-value 9-tap stencil on the diagonal (same rescale path as O)
        if (s0 < t0 + 64 + 4 && s0 + 64 > t0 - 4) {
#pragma unroll
            for (int i = 0; i < 4; i++) {
                const int t = t0 + ty * 4 + i;
#pragma unroll
                for (int dd = 0; dd < 9; dd++) {
                    const int s = t + dd - 4 - s0;
                    if (s >= 0 && s < 64) {
                        const float p = sP[(ty * 4 + i) * TS + s];
#pragma unroll
                        for (int j = 0; j < 4; j++)
                            acc[i][j] += p * sEV[dd * 64 + tx * 4 + j];
                    }
                }
            }
        }
    }

    // finalize: normalize, transpose through smem, write [b, h*64+kc, t]
    __syncthreads();
#pragma unroll
    for (int i = 0; i < 4; i++) {
        const float inv = 1.f / l_r[i];
#pragma unroll
        for (int j = 0; j < 4; j++)
            sP[(tx * 4 + j) * TS + ty * 4 + i] = acc[i][j] * inv;  // [kc][t]
    }
    __syncthreads();
    for (int i = tid; i < 4096; i += 256) {
        const int kc = i >> 6, t = i & 63;
        d_A[qbase + (size_t)kc * Tv + t0 + t] = sP[kc * TS + t];
    }
}

// ---------------------------------------------------------------------------

static const int ATTN_SMEM = (4 * 64 * TS + 576 + 576 + 64 * 12 + 513) * (int)sizeof(float);

extern "C" void kernel_launch(void* const* d_in, const int* in_sizes, int n_in,
                              void* d_out, int out_size)
{
    const float* x    = (const float*)d_in[0];
    const float* c    = (const float*)d_in[1];
    const float* mask = (const float*)d_in[2];
    const float* Wq   = (const float*)d_in[3];
    const float* bq   = (const float*)d_in[4];
    const float* Wk   = (const float*)d_in[5];
    const float* bk   = (const float*)d_in[6];
    const float* Wv   = (const float*)d_in[7];
    const float* bv   = (const float*)d_in[8];
    const float* Wo   = (const float*)d_in[9];
    const float* bo   = (const float*)d_in[10];
    const float* ek   = (const float*)d_in[11];
    const float* ev   = (const float*)d_in[12];
    float* out = (float*)d_out;

    float *Qp, *Kp, *Vp, *Ap;
    cudaGetSymbolAddress((void**)&Qp, d_Q);
    cudaGetSymbolAddress((void**)&Kp, d_K);
    cudaGetSymbolAddress((void**)&Vp, d_V);
    cudaGetSymbolAddress((void**)&Ap, d_A);

    cudaFuncSetAttribute(attn_kernel, cudaFuncAttributeMaxDynamicSharedMemorySize,
                         ATTN_SMEM);

    dim3 gg(Tv / 64, Cv / 64, Bv);
    proj_gemm<<<gg, 256>>>(Wq, bq, x, Qp, 0.125f);  // pre-scale Q by 1/sqrt(KC)
    proj_gemm<<<gg, 256>>>(Wk, bk, c, Kp, 1.0f);
    proj_gemm<<<gg, 256>>>(Wv, bv, c, Vp, 1.0f);

    dim3 ga(Tv / 64, Hh, Bv);
    attn_kernel<<<ga, 256, ATTN_SMEM>>>(mask, ek, ev);

    proj_gemm<<<gg, 256>>>(Wo, bo, Ap, out, 1.0f);
}

// round 5
// speedup vs baseline: 1.5040x; 1.5040x over previous
#include <cuda_runtime.h>
#include <cuda_bf16.h>
#include <math.h>
#include <stdint.h>

#define Bv 8
#define Cv 512
#define Tv 1024
#define Hh 8
#define KCv 64
#define TS 65   // attention smem tile stride

// ---------------------------------------------------------------------------
// Scratch (allocation-free rule: __device__ globals)
// ---------------------------------------------------------------------------
__device__ float d_Q[Bv * Cv * Tv];
__device__ float d_K[Bv * Cv * Tv];
__device__ float d_V[Bv * Cv * Tv];
__device__ float d_A[Bv * Cv * Tv];

// split-bf16 operands
__device__ __nv_bfloat16 g_Whi[4 * Cv * Cv];
__device__ __nv_bfloat16 g_Wlo[4 * Cv * Cv];
__device__ __nv_bfloat16 g_Bhi[Bv * Tv * Cv];   // transposed x (reused for A)
__device__ __nv_bfloat16 g_Blo[Bv * Tv * Cv];
__device__ __nv_bfloat16 g_Chi[Bv * Tv * Cv];   // transposed c
__device__ __nv_bfloat16 g_Clo[Bv * Tv * Cv];

// ---------------------------------------------------------------------------
// mma.sync m16n8k16 bf16 -> f32 (classic HMMA; works on plain sm_103 target)
// ---------------------------------------------------------------------------
#define MMA16816(d, a, b) \
    asm volatile("mma.sync.aligned.m16n8k16.row.col.f32.bf16.bf16.f32 " \
        "{%0,%1,%2,%3}, {%4,%5,%6,%7}, {%8,%9}, {%0,%1,%2,%3};" \
        : "+f"((d)[0]), "+f"((d)[1]), "+f"((d)[2]), "+f"((d)[3]) \
        : "r"((a)[0]), "r"((a)[1]), "r"((a)[2]), "r"((a)[3]), \
          "r"((b)[0]), "r"((b)[1]))

// ---------------------------------------------------------------------------
// fp32 -> (hi, lo) bf16 split, elementwise (weights)
// ---------------------------------------------------------------------------
__global__ __launch_bounds__(256) void convw_kernel(
    const float* __restrict__ w, __nv_bfloat16* __restrict__ hi, __nv_bfloat16* __restrict__ lo)
{
    const int i = blockIdx.x * 256 + threadIdx.x;
    const float v = w[i];
    const __nv_bfloat16 h = __float2bfloat16(v);
    hi[i] = h;
    lo[i] = __float2bfloat16(v - __bfloat162float(h));
}

// ---------------------------------------------------------------------------
// [b][c][t] fp32 -> [b][t][c] bf16 hi/lo (transpose + split)
// grid (T/32, C/32, B), block (32, 8)
// ---------------------------------------------------------------------------
__global__ __launch_bounds__(256) void tconv_kernel(
    const float* __restrict__ in, __nv_bfloat16* __restrict__ hi, __nv_bfloat16* __restrict__ lo)
{
    __shared__ float tile[32][33];
    const int b = blockIdx.z, c0 = blockIdx.y * 32, t0 = blockIdx.x * 32;
    const int tx = threadIdx.x, ty = threadIdx.y;
    const float* src = in + ((size_t)b * Cv + c0) * Tv + t0;
#pragma unroll
    for (int i = ty; i < 32; i += 8)
        tile[i][tx] = src[(size_t)i * Tv + tx];
    __syncthreads();
#pragma unroll
    for (int i = ty; i < 32; i += 8) {
        const float v = tile[tx][i];
        const size_t o = ((size_t)b * Tv + t0 + i) * Cv + c0 + tx;
        const __nv_bfloat16 h = __float2bfloat16(v);
        hi[o] = h;
        lo[o] = __float2bfloat16(v - __bfloat162float(h));
    }
}

// ---------------------------------------------------------------------------
// HMMA split-bf16 projection GEMM.
// out[b,o,t] = (sum_c W[o,c]*in[c,t] + bias[o]) * scale, fp32-equivalent accuracy.
// A[m=o, k=c] = W hi/lo (K contig); B[n=t, k=c] = transposed input hi/lo (K contig).
// grid (T/128, C/128, B), block 256 (8 warps, 2x4), warp tile 64x32, K chunk 32.
// D = Ah*Bh + Ah*Bl + Al*Bh with fp32 register accumulators.
// ---------------------------------------------------------------------------
#define KCH 32
#define SSTR 40   // smem row stride in bf16 (32 + 8 pad -> conflict-free)

__global__ __launch_bounds__(256) void hmma_proj(
    const __nv_bfloat16* __restrict__ Ahi, const __nv_bfloat16* __restrict__ Alo,
    const __nv_bfloat16* __restrict__ Bhi, const __nv_bfloat16* __restrict__ Blo,
    const float* __restrict__ bias, float* __restrict__ out, float scale)
{
    __shared__ __nv_bfloat16 sAh[128 * SSTR];
    __shared__ __nv_bfloat16 sAl[128 * SSTR];
    __shared__ __nv_bfloat16 sBh[128 * SSTR];
    __shared__ __nv_bfloat16 sBl[128 * SSTR];

    const int t0 = blockIdx.x * 128, o0 = blockIdx.y * 128, b = blockIdx.z;
    const int tid = threadIdx.x, wid = tid >> 5, lid = tid & 31;
    const int wm = wid >> 2, wn = wid & 3;           // warp grid 2x4
    const int m0 = wm * 64, n0 = wn * 32;
    const int g = lid >> 2, tg = lid & 3;

    float acc[4][4][4];
#pragma unroll
    for (int mi = 0; mi < 4; mi++)
#pragma unroll
        for (int nj = 0; nj < 4; nj++)
#pragma unroll
            for (int r = 0; r < 4; r++) acc[mi][nj][r] = 0.f;

    const __nv_bfloat16* Bhi_b = Bhi + ((size_t)b * Tv + t0) * Cv;
    const __nv_bfloat16* Blo_b = Blo + ((size_t)b * Tv + t0) * Cv;

    for (int kc0 = 0; kc0 < Cv; kc0 += KCH) {
        __syncthreads();
#pragma unroll
        for (int u = 0; u < 2; u++) {
            const int idx = tid + u * 256;       // 0..511
            const int r = idx >> 2, c8 = (idx & 3) * 8;
            *reinterpret_cast<uint4*>(&sAh[r * SSTR + c8]) =
                *reinterpret_cast<const uint4*>(&Ahi[(size_t)(o0 + r) * Cv + kc0 + c8]);
            *reinterpret_cast<uint4*>(&sAl[r * SSTR + c8]) =
                *reinterpret_cast<const uint4*>(&Alo[(size_t)(o0 + r) * Cv + kc0 + c8]);
            *reinterpret_cast<uint4*>(&sBh[r * SSTR + c8]) =
                *reinterpret_cast<const uint4*>(&Bhi_b[(size_t)r * Cv + kc0 + c8]);
            *reinterpret_cast<uint4*>(&sBl[r * SSTR + c8]) =
                *reinterpret_cast<const uint4*>(&Blo_b[(size_t)r * Cv + kc0 + c8]);
        }
        __syncthreads();

#pragma unroll
        for (int ks = 0; ks < KCH; ks += 16) {
            const int kk = ks + tg * 2;
            uint32_t ah[4][4], al[4][4], bh[4][2], bl[4][2];
#pragma unroll
            for (int mi = 0; mi < 4; mi++) {
                const int row = m0 + mi * 16 + g;
                ah[mi][0] = *reinterpret_cast<const uint32_t*>(&sAh[row * SSTR + kk]);
                ah[mi][1] = *reinterpret_cast<const uint32_t*>(&sAh[(row + 8) * SSTR + kk]);
                ah[mi][2] = *reinterpret_cast<const uint32_t*>(&sAh[row * SSTR + kk + 8]);
                ah[mi][3] = *reinterpret_cast<const uint32_t*>(&sAh[(row + 8) * SSTR + kk + 8]);
                al[mi][0] = *reinterpret_cast<const uint32_t*>(&sAl[row * SSTR + kk]);
                al[mi][1] = *reinterpret_cast<const uint32_t*>(&sAl[(row + 8) * SSTR + kk]);
                al[mi][2] = *reinterpret_cast<const uint32_t*>(&sAl[row * SSTR + kk + 8]);
                al[mi][3] = *reinterpret_cast<const uint32_t*>(&sAl[(row + 8) * SSTR + kk + 8]);
            }
#pragma unroll
            for (int nj = 0; nj < 4; nj++) {
                const int col = n0 + nj * 8 + g;
                bh[nj][0] = *reinterpret_cast<const uint32_t*>(&sBh[col * SSTR + kk]);
                bh[nj][1] = *reinterpret_cast<const uint32_t*>(&sBh[col * SSTR + kk + 8]);
                bl[nj][0] = *reinterpret_cast<const uint32_t*>(&sBl[col * SSTR + kk]);
                bl[nj][1] = *reinterpret_cast<const uint32_t*>(&sBl[col * SSTR + kk + 8]);
            }
#pragma unroll
            for (int mi = 0; mi < 4; mi++)
#pragma unroll
                for (int nj = 0; nj < 4; nj++) {
                    MMA16816(acc[mi][nj], ah[mi], bh[nj]);
                    MMA16816(acc[mi][nj], ah[mi], bl[nj]);
                    MMA16816(acc[mi][nj], al[mi], bh[nj]);
                }
        }
    }

    // Epilogue: d frag = (g,2t),(g,2t+1),(g+8,2t),(g+8,2t+1)
#pragma unroll
    for (int mi = 0; mi < 4; mi++) {
        const int o = o0 + m0 + mi * 16 + g;
        const float b0 = bias[o], b1 = bias[o + 8];
#pragma unroll
        for (int nj = 0; nj < 4; nj++) {
            const int t = t0 + n0 + nj * 8 + tg * 2;
            float2 v0, v1;
            v0.x = (acc[mi][nj][0] + b0) * scale;
            v0.y = (acc[mi][nj][1] + b0) * scale;
            v1.x = (acc[mi][nj][2] + b1) * scale;
            v1.y = (acc[mi][nj][3] + b1) * scale;
            *reinterpret_cast<float2*>(&out[((size_t)b * Cv + o) * Tv + t]) = v0;
            *reinterpret_cast<float2*>(&out[((size_t)b * Cv + o + 8) * Tv + t]) = v1;
        }
    }
}

// ---------------------------------------------------------------------------
// Banded flash attention with relative-position logits/values + proximal bias.
// grid: (T/64, H, B), block 256 (16x16 threads, 4x4 micro-tiles).
// Q already pre-scaled by 1/sqrt(KC) at projection time.
// ---------------------------------------------------------------------------
__global__ __launch_bounds__(256) void attn_kernel(
    const float* __restrict__ mask, const float* __restrict__ ek,
    const float* __restrict__ ev)
{
    extern __shared__ float sm[];
    float* sQ    = sm;              // [kc][t] stride TS
    float* sK    = sQ + 64 * TS;    // [kc][s] stride TS
    float* sV    = sK + 64 * TS;    // [s][kc] stride TS
    float* sP    = sV + 64 * TS;    // [t][s]  stride TS (reused as [kc][t] at end)
    float* sEK   = sP + 64 * TS;    // [9][64]
    float* sEV   = sEK + 576;       // [9][64]
    float* sRK   = sEV + 576;       // [t][d] stride 12
    float* sBias = sRK + 64 * 12;   // [513]: -log1p(|d|), d = i-256

    const int t0 = blockIdx.x * 64;
    const int h  = blockIdx.y;
    const int b  = blockIdx.z;
    const int tid = threadIdx.x;
    const int ty = tid >> 4, tx = tid & 15;

    const size_t qbase = ((size_t)b * Cv + h * KCv) * Tv;

    for (int i = tid; i < 4096; i += 256) {
        const int kc = i >> 6, t = i & 63;
        sQ[kc * TS + t] = d_Q[qbase + (size_t)kc * Tv + t0 + t];
    }
    for (int i = tid; i < 576; i += 256) { sEK[i] = ek[i]; sEV[i] = ev[i]; }
    for (int i = tid; i < 513; i += 256)
        sBias[i] = -log1pf(fabsf((float)(i - 256)));
    __syncthreads();

    for (int i = tid; i < 576; i += 256) {
        const int t = i & 63, dd = i >> 6;
        float s = 0.f;
#pragma unroll 16
        for (int kc = 0; kc < 64; kc++) s += sQ[kc * TS + t] * sEK[dd * 64 + kc];
        sRK[t * 12 + dd] = s;
    }

    float m_r[4], l_r[4], acc[4][4];
#pragma unroll
    for (int i = 0; i < 4; i++) {
        m_r[i] = -1e30f; l_r[i] = 0.f;
#pragma unroll
        for (int j = 0; j < 4; j++) acc[i][j] = 0.f;
    }

    const int s_lo = max(0, t0 - 256);
    const int s_hi = min(Tv, t0 + 64 + 256);
    const size_t mbase = (size_t)b * Tv * Tv;

    for (int s0 = s_lo; s0 < s_hi; s0 += 64) {
        __syncthreads();
        for (int i = tid; i < 4096; i += 256) {
            const int kc = i >> 6, s = i & 63;
            const float kval = d_K[qbase + (size_t)kc * Tv + s0 + s];
            const float vval = d_V[qbase + (size_t)kc * Tv + s0 + s];
            sK[kc * TS + s] = kval;
            sV[s * TS + kc] = vval;
        }
        __syncthreads();

        float sv[4][4];
#pragma unroll
        for (int i = 0; i < 4; i++)
#pragma unroll
            for (int j = 0; j < 4; j++) sv[i][j] = 0.f;
#pragma unroll 8
        for (int kc = 0; kc < 64; kc++) {
            float qv[4], kv[4];
#pragma unroll
            for (int i = 0; i < 4; i++) qv[i] = sQ[kc * TS + ty * 4 + i];
#pragma unroll
            for (int j = 0; j < 4; j++) kv[j] = sK[kc * TS + tx * 4 + j];
#pragma unroll
            for (int i = 0; i < 4; i++)
#pragma unroll
                for (int j = 0; j < 4; j++) sv[i][j] += qv[i] * kv[j];
        }

#pragma unroll
        for (int i = 0; i < 4; i++) {
            const int t = t0 + ty * 4 + i;
#pragma unroll
            for (int j = 0; j < 4; j++) {
                const int s = s0 + tx * 4 + j;
                const int d = s - t;
                float val;
                if (d >= -256 && d <= 256) {
                    val = sv[i][j] + sBias[d + 256];
                    if (d >= -4 && d <= 4) val += sRK[(ty * 4 + i) * 12 + d + 4];
                    if (mask[mbase + (size_t)t * Tv + s] == 0.f) val = -1e30f;
                } else {
                    val = -1e30f;
                }
                sv[i][j] = val;
            }
        }

        float scale_r[4];
#pragma unroll
        for (int i = 0; i < 4; i++) {
            float rm = fmaxf(fmaxf(sv[i][0], sv[i][1]), fmaxf(sv[i][2], sv[i][3]));
            rm = fmaxf(rm, __shfl_xor_sync(0xffffffffu, rm, 8));
            rm = fmaxf(rm, __shfl_xor_sync(0xffffffffu, rm, 4));
            rm = fmaxf(rm, __shfl_xor_sync(0xffffffffu, rm, 2));
            rm = fmaxf(rm, __shfl_xor_sync(0xffffffffu, rm, 1));
            const float mn = fmaxf(m_r[i], rm);
            const float sc = __expf(m_r[i] - mn);
            float rs = 0.f;
#pragma unroll
            for (int j = 0; j < 4; j++) {
                const float p = __expf(sv[i][j] - mn);
                sv[i][j] = p;
                rs += p;
            }
            rs += __shfl_xor_sync(0xffffffffu, rs, 8);
            rs += __shfl_xor_sync(0xffffffffu, rs, 4);
            rs += __shfl_xor_sync(0xffffffffu, rs, 2);
            rs += __shfl_xor_sync(0xffffffffu, rs, 1);
            l_r[i] = l_r[i] * sc + rs;
            m_r[i] = mn;
            scale_r[i] = sc;
        }

#pragma unroll
        for (int i = 0; i < 4; i++)
#pragma unroll
            for (int j = 0; j < 4; j++)
                sP[(ty * 4 + i) * TS + tx * 4 + j] = sv[i][j];
        __syncthreads();

#pragma unroll
        for (int i = 0; i < 4; i++)
#pragma unroll
            for (int j = 0; j < 4; j++) acc[i][j] *= scale_r[i];
#pragma unroll 4
        for (int s = 0; s < 64; s++) {
            float pv[4], vv[4];
#pragma unroll
            for (int i = 0; i < 4; i++) pv[i] = sP[(ty * 4 + i) * TS + s];
#pragma unroll
            for (int j = 0; j < 4; j++) vv[j] = sV[s * TS + tx * 4 + j];
#pragma unroll
            for (int i = 0; i < 4; i++)
#pragma unroll
                for (int j = 0; j < 4; j++) acc[i][j] += pv[i] * vv[j];
        }

        if (s0 < t0 + 64 + 4 && s0 + 64 > t0 - 4) {
#pragma unroll
            for (int i = 0; i < 4; i++) {
                const int t = t0 + ty * 4 + i;
#pragma unroll
                for (int dd = 0; dd < 9; dd++) {
                    const int s = t + dd - 4 - s0;
                    if (s >= 0 && s < 64) {
                        const float p = sP[(ty * 4 + i) * TS + s];
#pragma unroll
                        for (int j = 0; j < 4; j++)
                            acc[i][j] += p * sEV[dd * 64 + tx * 4 + j];
                    }
                }
            }
        }
    }

    __syncthreads();
#pragma unroll
    for (int i = 0; i < 4; i++) {
        const float inv = 1.f / l_r[i];
#pragma unroll
        for (int j = 0; j < 4; j++)
            sP[(tx * 4 + j) * TS + ty * 4 + i] = acc[i][j] * inv;
    }
    __syncthreads();
    for (int i = tid; i < 4096; i += 256) {
        const int kc = i >> 6, t = i & 63;
        d_A[qbase + (size_t)kc * Tv + t0 + t] = sP[kc * TS + t];
    }
}

// ---------------------------------------------------------------------------

static const int ATTN_SMEM = (4 * 64 * TS + 576 + 576 + 64 * 12 + 513) * (int)sizeof(float);

extern "C" void kernel_launch(void* const* d_in, const int* in_sizes, int n_in,
                              void* d_out, int out_size)
{
    const float* x    = (const float*)d_in[0];
    const float* c    = (const float*)d_in[1];
    const float* mask = (const float*)d_in[2];
    const float* Wq   = (const float*)d_in[3];
    const float* bq   = (const float*)d_in[4];
    const float* Wk   = (const float*)d_in[5];
    const float* bk   = (const float*)d_in[6];
    const float* Wv   = (const float*)d_in[7];
    const float* bv   = (const float*)d_in[8];
    const float* Wo   = (const float*)d_in[9];
    const float* bo   = (const float*)d_in[10];
    const float* ek   = (const float*)d_in[11];
    const float* ev   = (const float*)d_in[12];
    float* out = (float*)d_out;

    float *Qp, *Kp, *Vp, *Ap;
    __nv_bfloat16 *whi, *wlo, *bhi, *blo, *chi, *clo;
    cudaGetSymbolAddress((void**)&Qp, d_Q);
    cudaGetSymbolAddress((void**)&Kp, d_K);
    cudaGetSymbolAddress((void**)&Vp, d_V);
    cudaGetSymbolAddress((void**)&Ap, d_A);
    cudaGetSymbolAddress((void**)&whi, g_Whi);
    cudaGetSymbolAddress((void**)&wlo, g_Wlo);
    cudaGetSymbolAddress((void**)&bhi, g_Bhi);
    cudaGetSymbolAddress((void**)&blo, g_Blo);
    cudaGetSymbolAddress((void**)&chi, g_Chi);
    cudaGetSymbolAddress((void**)&clo, g_Clo);

    cudaFuncSetAttribute(attn_kernel, cudaFuncAttributeMaxDynamicSharedMemorySize, ATTN_SMEM);

    const int WSZ = Cv * Cv;  // 262144

    // weight splits
    convw_kernel<<<WSZ / 256, 256>>>(Wq, whi + 0 * WSZ, wlo + 0 * WSZ);
    convw_kernel<<<WSZ / 256, 256>>>(Wk, whi + 1 * WSZ, wlo + 1 * WSZ);
    convw_kernel<<<WSZ / 256, 256>>>(Wv, whi + 2 * WSZ, wlo + 2 * WSZ);
    convw_kernel<<<WSZ / 256, 256>>>(Wo, whi + 3 * WSZ, wlo + 3 * WSZ);

    // activation transposed splits
    dim3 tg(Tv / 32, Cv / 32, Bv), tb(32, 8);
    tconv_kernel<<<tg, tb>>>(x, bhi, blo);
    tconv_kernel<<<tg, tb>>>(c, chi, clo);

    // projections (Q pre-scaled by 1/sqrt(KC))
    dim3 gg(Tv / 128, Cv / 128, Bv);
    hmma_proj<<<gg, 256>>>(whi + 0 * WSZ, wlo + 0 * WSZ, bhi, blo, bq, Qp, 0.125f);
    hmma_proj<<<gg, 256>>>(whi + 1 * WSZ, wlo + 1 * WSZ, chi, clo, bk, Kp, 1.0f);
    hmma_proj<<<gg, 256>>>(whi + 2 * WSZ, wlo + 2 * WSZ, chi, clo, bv, Vp, 1.0f);

    // attention
    dim3 ga(Tv / 64, Hh, Bv);
    attn_kernel<<<ga, 256, ATTN_SMEM>>>(mask, ek, ev);

    // output projection (reuse x's transposed buffers for A)
    tconv_kernel<<<tg, tb>>>(Ap, bhi, blo);
    hmma_proj<<<gg, 256>>>(whi + 3 * WSZ, wlo + 3 * WSZ, bhi, blo, bo, out, 1.0f);
}

// round 6
// speedup vs baseline: 1.5496x; 1.0303x over previous
#include <cuda_runtime.h>
#include <cuda_bf16.h>
#include <math.h>
#include <stdint.h>

#define Bv 8
#define Cv 512
#define Tv 1024
#define Hh 8
#define KCv 64

// ---------------------------------------------------------------------------
// Scratch (allocation-free rule: __device__ globals)
// ---------------------------------------------------------------------------
__device__ float d_Q[Bv * Cv * Tv];
__device__ float d_K[Bv * Cv * Tv];
__device__ float d_V[Bv * Cv * Tv];
__device__ float d_A[Bv * Cv * Tv];

// split-bf16 operands
__device__ __nv_bfloat16 g_Whi[4 * Cv * Cv];
__device__ __nv_bfloat16 g_Wlo[4 * Cv * Cv];
__device__ __nv_bfloat16 g_Bhi[Bv * Tv * Cv];   // transposed x (reused for A)
__device__ __nv_bfloat16 g_Blo[Bv * Tv * Cv];
__device__ __nv_bfloat16 g_Chi[Bv * Tv * Cv];   // transposed c
__device__ __nv_bfloat16 g_Clo[Bv * Tv * Cv];

// ---------------------------------------------------------------------------
// mma.sync m16n8k16 bf16 -> f32 (classic HMMA; works on plain sm_103 target)
// ---------------------------------------------------------------------------
#define MMA16816(d, a, b) \
    asm volatile("mma.sync.aligned.m16n8k16.row.col.f32.bf16.bf16.f32 " \
        "{%0,%1,%2,%3}, {%4,%5,%6,%7}, {%8,%9}, {%0,%1,%2,%3};" \
        : "+f"((d)[0]), "+f"((d)[1]), "+f"((d)[2]), "+f"((d)[3]) \
        : "r"((a)[0]), "r"((a)[1]), "r"((a)[2]), "r"((a)[3]), \
          "r"((b)[0]), "r"((b)[1]))

__device__ __forceinline__ uint32_t ldb32(const __nv_bfloat16* p) {
    return *reinterpret_cast<const uint32_t*>(p);
}
__device__ __forceinline__ void pack_pair(float x, float y, uint32_t& hi, uint32_t& lo) {
    const __nv_bfloat16 hx = __float2bfloat16(x), hy = __float2bfloat16(y);
    const __nv_bfloat16 lx = __float2bfloat16(x - __bfloat162float(hx));
    const __nv_bfloat16 ly = __float2bfloat16(y - __bfloat162float(hy));
    __nv_bfloat162 h2; h2.x = hx; h2.y = hy;
    __nv_bfloat162 l2; l2.x = lx; l2.y = ly;
    hi = *reinterpret_cast<const uint32_t*>(&h2);
    lo = *reinterpret_cast<const uint32_t*>(&l2);
}

// ---------------------------------------------------------------------------
// fp32 -> (hi, lo) bf16 split for 4 weight matrices in one launch
// grid (C*C/256, 4)
// ---------------------------------------------------------------------------
__global__ __launch_bounds__(256) void convw4_kernel(
    const float* __restrict__ w0, const float* __restrict__ w1,
    const float* __restrict__ w2, const float* __restrict__ w3,
    __nv_bfloat16* __restrict__ hi, __nv_bfloat16* __restrict__ lo)
{
    const int m = blockIdx.y;
    const float* w = (m == 0) ? w0 : (m == 1) ? w1 : (m == 2) ? w2 : w3;
    const int i = blockIdx.x * 256 + threadIdx.x;
    const float v = w[i];
    const __nv_bfloat16 h = __float2bfloat16(v);
    hi[m * Cv * Cv + i] = h;
    lo[m * Cv * Cv + i] = __float2bfloat16(v - __bfloat162float(h));
}

// ---------------------------------------------------------------------------
// [b][c][t] fp32 -> [b][t][c] bf16 hi/lo (transpose + split)
// grid (T/32, C/32, B), block (32, 8)
// ---------------------------------------------------------------------------
__global__ __launch_bounds__(256) void tconv_kernel(
    const float* __restrict__ in, __nv_bfloat16* __restrict__ hi, __nv_bfloat16* __restrict__ lo)
{
    __shared__ float tile[32][33];
    const int b = blockIdx.z, c0 = blockIdx.y * 32, t0 = blockIdx.x * 32;
    const int tx = threadIdx.x, ty = threadIdx.y;
    const float* src = in + ((size_t)b * Cv + c0) * Tv + t0;
#pragma unroll
    for (int i = ty; i < 32; i += 8)
        tile[i][tx] = src[(size_t)i * Tv + tx];
    __syncthreads();
#pragma unroll
    for (int i = ty; i < 32; i += 8) {
        const float v = tile[tx][i];
        const size_t o = ((size_t)b * Tv + t0 + i) * Cv + c0 + tx;
        const __nv_bfloat16 h = __float2bfloat16(v);
        hi[o] = h;
        lo[o] = __float2bfloat16(v - __bfloat162float(h));
    }
}

// ---------------------------------------------------------------------------
// HMMA split-bf16 projection GEMM (unchanged from R5; passing).
// ---------------------------------------------------------------------------
#define KCH 32
#define SSTR 40

__global__ __launch_bounds__(256) void hmma_proj(
    const __nv_bfloat16* __restrict__ Ahi, const __nv_bfloat16* __restrict__ Alo,
    const __nv_bfloat16* __restrict__ Bhi, const __nv_bfloat16* __restrict__ Blo,
    const float* __restrict__ bias, float* __restrict__ out, float scale)
{
    __shared__ __nv_bfloat16 sAh[128 * SSTR];
    __shared__ __nv_bfloat16 sAl[128 * SSTR];
    __shared__ __nv_bfloat16 sBh[128 * SSTR];
    __shared__ __nv_bfloat16 sBl[128 * SSTR];

    const int t0 = blockIdx.x * 128, o0 = blockIdx.y * 128, b = blockIdx.z;
    const int tid = threadIdx.x, wid = tid >> 5, lid = tid & 31;
    const int wm = wid >> 2, wn = wid & 3;
    const int m0 = wm * 64, n0 = wn * 32;
    const int g = lid >> 2, tg = lid & 3;

    float acc[4][4][4];
#pragma unroll
    for (int mi = 0; mi < 4; mi++)
#pragma unroll
        for (int nj = 0; nj < 4; nj++)
#pragma unroll
            for (int r = 0; r < 4; r++) acc[mi][nj][r] = 0.f;

    const __nv_bfloat16* Bhi_b = Bhi + ((size_t)b * Tv + t0) * Cv;
    const __nv_bfloat16* Blo_b = Blo + ((size_t)b * Tv + t0) * Cv;

    for (int kc0 = 0; kc0 < Cv; kc0 += KCH) {
        __syncthreads();
#pragma unroll
        for (int u = 0; u < 2; u++) {
            const int idx = tid + u * 256;
            const int r = idx >> 2, c8 = (idx & 3) * 8;
            *reinterpret_cast<uint4*>(&sAh[r * SSTR + c8]) =
                *reinterpret_cast<const uint4*>(&Ahi[(size_t)(o0 + r) * Cv + kc0 + c8]);
            *reinterpret_cast<uint4*>(&sAl[r * SSTR + c8]) =
                *reinterpret_cast<const uint4*>(&Alo[(size_t)(o0 + r) * Cv + kc0 + c8]);
            *reinterpret_cast<uint4*>(&sBh[r * SSTR + c8]) =
                *reinterpret_cast<const uint4*>(&Bhi_b[(size_t)r * Cv + kc0 + c8]);
            *reinterpret_cast<uint4*>(&sBl[r * SSTR + c8]) =
                *reinterpret_cast<const uint4*>(&Blo_b[(size_t)r * Cv + kc0 + c8]);
        }
        __syncthreads();

#pragma unroll
        for (int ks = 0; ks < KCH; ks += 16) {
            const int kk = ks + tg * 2;
            uint32_t ah[4][4], al[4][4], bh[4][2], bl[4][2];
#pragma unroll
            for (int mi = 0; mi < 4; mi++) {
                const int row = m0 + mi * 16 + g;
                ah[mi][0] = ldb32(&sAh[row * SSTR + kk]);
                ah[mi][1] = ldb32(&sAh[(row + 8) * SSTR + kk]);
                ah[mi][2] = ldb32(&sAh[row * SSTR + kk + 8]);
                ah[mi][3] = ldb32(&sAh[(row + 8) * SSTR + kk + 8]);
                al[mi][0] = ldb32(&sAl[row * SSTR + kk]);
                al[mi][1] = ldb32(&sAl[(row + 8) * SSTR + kk]);
                al[mi][2] = ldb32(&sAl[row * SSTR + kk + 8]);
                al[mi][3] = ldb32(&sAl[(row + 8) * SSTR + kk + 8]);
            }
#pragma unroll
            for (int nj = 0; nj < 4; nj++) {
                const int col = n0 + nj * 8 + g;
                bh[nj][0] = ldb32(&sBh[col * SSTR + kk]);
                bh[nj][1] = ldb32(&sBh[col * SSTR + kk + 8]);
                bl[nj][0] = ldb32(&sBl[col * SSTR + kk]);
                bl[nj][1] = ldb32(&sBl[col * SSTR + kk + 8]);
            }
#pragma unroll
            for (int mi = 0; mi < 4; mi++)
#pragma unroll
                for (int nj = 0; nj < 4; nj++) {
                    MMA16816(acc[mi][nj], ah[mi], bh[nj]);
                    MMA16816(acc[mi][nj], ah[mi], bl[nj]);
                    MMA16816(acc[mi][nj], al[mi], bh[nj]);
                }
        }
    }

#pragma unroll
    for (int mi = 0; mi < 4; mi++) {
        const int o = o0 + m0 + mi * 16 + g;
        const float b0 = bias[o], b1 = bias[o + 8];
#pragma unroll
        for (int nj = 0; nj < 4; nj++) {
            const int t = t0 + n0 + nj * 8 + tg * 2;
            float2 v0, v1;
            v0.x = (acc[mi][nj][0] + b0) * scale;
            v0.y = (acc[mi][nj][1] + b0) * scale;
            v1.x = (acc[mi][nj][2] + b1) * scale;
            v1.y = (acc[mi][nj][3] + b1) * scale;
            *reinterpret_cast<float2*>(&out[((size_t)b * Cv + o) * Tv + t]) = v0;
            *reinterpret_cast<float2*>(&out[((size_t)b * Cv + o + 8) * Tv + t]) = v1;
        }
    }
}

// ---------------------------------------------------------------------------
// HMMA banded flash attention, split-bf16 3-term, 128 q-rows per CTA.
// grid (T/128, H, B), block 256 (8 warps x 16 rows).
// Q pre-scaled by 1/sqrt(KC).
// ---------------------------------------------------------------------------
#define QSTR 72   // smem bf16 row stride (36 words -> conflict-free frag loads)

// smem layout (element offsets within their type)
#define OFF_QH 0
#define OFF_QL (128 * QSTR)
#define OFF_KH (2 * 128 * QSTR)
#define OFF_KL (2 * 128 * QSTR + 64 * QSTR)
#define OFF_VH (2 * 128 * QSTR + 2 * 64 * QSTR)
#define OFF_VL (2 * 128 * QSTR + 3 * 64 * QSTR)
#define BF16_ELEMS (2 * 128 * QSTR + 4 * 64 * QSTR)
// float section starts after bf16 section
#define F_RK   0            // 128*12
#define F_BIAS (128 * 12)   // 516
#define F_EV   (128 * 12 + 516)          // 576
#define F_EK   (128 * 12 + 516 + 576)    // 576
#define F_PD   (128 * 12 + 516 + 2 * 576)// 128*12
#define F_TOTAL (2 * 128 * 12 + 516 + 2 * 576)
#define ATTN_SMEM_BYTES (BF16_ELEMS * 2 + F_TOTAL * 4)

__global__ __launch_bounds__(256, 1) void attn_hmma(
    const float* __restrict__ mask, const float* __restrict__ ek,
    const float* __restrict__ ev)
{
    extern __shared__ __align__(16) char smem_raw[];
    __nv_bfloat16* sB16 = reinterpret_cast<__nv_bfloat16*>(smem_raw);
    float* sF = reinterpret_cast<float*>(smem_raw + BF16_ELEMS * 2);
    __nv_bfloat16* sQh = sB16 + OFF_QH;
    __nv_bfloat16* sQl = sB16 + OFF_QL;
    __nv_bfloat16* sKh = sB16 + OFF_KH;
    __nv_bfloat16* sKl = sB16 + OFF_KL;
    __nv_bfloat16* sVh = sB16 + OFF_VH;
    __nv_bfloat16* sVl = sB16 + OFF_VL;
    float* sRK   = sF + F_RK;
    float* sBias = sF + F_BIAS;
    float* sEV   = sF + F_EV;
    float* sEK   = sF + F_EK;
    float* sPd   = sF + F_PD;
    float* sOut  = reinterpret_cast<float*>(smem_raw);  // alias Q area (64*132 floats)

    const int t0 = blockIdx.x * 128;
    const int h  = blockIdx.y;
    const int b  = blockIdx.z;
    const int tid = threadIdx.x, wid = tid >> 5, lid = tid & 31;
    const int g = lid >> 2, tg = lid & 3;
    const int wloc = wid * 16;

    const size_t qbase = ((size_t)b * Cv + h * KCv) * Tv;
    const size_t mbase = (size_t)b * Tv * Tv;

    // Load Q (transpose [kc][t] -> [t][kc], split hi/lo)
    for (int i = tid; i < 8192; i += 256) {
        const int t = i & 127, kc = i >> 7;
        const float v = d_Q[qbase + (size_t)kc * Tv + t0 + t];
        const __nv_bfloat16 hv = __float2bfloat16(v);
        sQh[t * QSTR + kc] = hv;
        sQl[t * QSTR + kc] = __float2bfloat16(v - __bfloat162float(hv));
    }
    for (int i = tid; i < 513; i += 256)
        sBias[i] = -log1pf(fabsf((float)(i - 256)));
    for (int i = tid; i < 576; i += 256) { sEK[i] = ek[i]; sEV[i] = ev[i]; }
    __syncthreads();

    // sRK[t][d] = sum_kc q[t][kc] * ek[d][kc]
    for (int i = tid; i < 1152; i += 256) {
        const int tl = i & 127, dd = i >> 7;
        float s = 0.f;
#pragma unroll 16
        for (int kc = 0; kc < 64; kc++) {
            const float q = __bfloat162float(sQh[tl * QSTR + kc]) +
                            __bfloat162float(sQl[tl * QSTR + kc]);
            s += q * sEK[dd * 64 + kc];
        }
        sRK[tl * 12 + dd] = s;
    }

    float m0 = -1e30f, m1 = -1e30f, l0 = 0.f, l1 = 0.f;
    float O[8][4];
#pragma unroll
    for (int nt = 0; nt < 8; nt++)
#pragma unroll
        for (int r = 0; r < 4; r++) O[nt][r] = 0.f;

    const int s_lo = max(0, t0 - 256);
    const int s_hi = min(Tv, t0 + 128 + 256);

    for (int s0 = s_lo; s0 < s_hi; s0 += 64) {
        const bool window = (s0 >= t0 - 64) && (s0 <= t0 + 128);
        __syncthreads();  // protect K/V/Pd from previous iteration readers
        if (window) {
            for (int i = tid; i < 1536; i += 256) sPd[i] = 0.f;
        }
        // K: [kc][t] -> sK[s][kc]
        for (int i = tid; i < 4096; i += 256) {
            const int s = i & 63, kc = i >> 6;
            const float v = d_K[qbase + (size_t)kc * Tv + s0 + s];
            const __nv_bfloat16 hv = __float2bfloat16(v);
            sKh[s * QSTR + kc] = hv;
            sKl[s * QSTR + kc] = __float2bfloat16(v - __bfloat162float(hv));
        }
        // V: [kc][t] -> sV[kc][s] (word-wise stores)
        for (int i = tid; i < 2048; i += 256) {
            const int sw = i & 31, kc = i >> 5;
            const float2 v2 = *reinterpret_cast<const float2*>(
                &d_V[qbase + (size_t)kc * Tv + s0 + 2 * sw]);
            uint32_t whi, wlo;
            pack_pair(v2.x, v2.y, whi, wlo);
            *reinterpret_cast<uint32_t*>(&sVh[kc * QSTR + 2 * sw]) = whi;
            *reinterpret_cast<uint32_t*>(&sVl[kc * QSTR + 2 * sw]) = wlo;
        }
        __syncthreads();

        // ---- S = Q K^T ----
        float S[8][4];
#pragma unroll
        for (int nt = 0; nt < 8; nt++)
#pragma unroll
            for (int r = 0; r < 4; r++) S[nt][r] = 0.f;

#pragma unroll
        for (int ks = 0; ks < 4; ks++) {
            const int qr = (wloc + g) * QSTR + ks * 16 + tg * 2;
            uint32_t aqh[4], aql[4];
            aqh[0] = ldb32(&sQh[qr]);
            aqh[1] = ldb32(&sQh[qr + 8 * QSTR]);
            aqh[2] = ldb32(&sQh[qr + 8]);
            aqh[3] = ldb32(&sQh[qr + 8 * QSTR + 8]);
            aql[0] = ldb32(&sQl[qr]);
            aql[1] = ldb32(&sQl[qr + 8 * QSTR]);
            aql[2] = ldb32(&sQl[qr + 8]);
            aql[3] = ldb32(&sQl[qr + 8 * QSTR + 8]);
#pragma unroll
            for (int nt = 0; nt < 8; nt++) {
                const int kr = (nt * 8 + g) * QSTR + ks * 16 + tg * 2;
                uint32_t bh[2], bl[2];
                bh[0] = ldb32(&sKh[kr]);
                bh[1] = ldb32(&sKh[kr + 8]);
                bl[0] = ldb32(&sKl[kr]);
                bl[1] = ldb32(&sKl[kr + 8]);
                MMA16816(S[nt], aqh, bh);
                MMA16816(S[nt], aqh, bl);
                MMA16816(S[nt], aql, bh);
            }
        }

        // ---- biases + band + mask ----
#pragma unroll
        for (int nt = 0; nt < 8; nt++) {
#pragma unroll
            for (int r = 0; r < 4; r++) {
                const int tlr = wloc + g + ((r >> 1) << 3);
                const int t = t0 + tlr;
                const int s = s0 + nt * 8 + tg * 2 + (r & 1);
                const int d = s - t;
                float v = S[nt][r];
                if (d >= -256 && d <= 256) {
                    v += sBias[d + 256];
                    if (d >= -4 && d <= 4) v += sRK[tlr * 12 + d + 4];
                    if (mask[mbase + (size_t)t * Tv + s] == 0.f) v = -1e4f;
                } else {
                    v = -2e30f;   // distinct from m_init: exp always underflows to 0
                }
                S[nt][r] = v;
            }
        }

        // ---- online softmax (rows g / g+8, quad shfl over tg) ----
        float rm0 = -2e30f, rm1 = -2e30f;
#pragma unroll
        for (int nt = 0; nt < 8; nt++) {
            rm0 = fmaxf(rm0, fmaxf(S[nt][0], S[nt][1]));
            rm1 = fmaxf(rm1, fmaxf(S[nt][2], S[nt][3]));
        }
        rm0 = fmaxf(rm0, __shfl_xor_sync(0xffffffffu, rm0, 1));
        rm0 = fmaxf(rm0, __shfl_xor_sync(0xffffffffu, rm0, 2));
        rm1 = fmaxf(rm1, __shfl_xor_sync(0xffffffffu, rm1, 1));
        rm1 = fmaxf(rm1, __shfl_xor_sync(0xffffffffu, rm1, 2));
        const float mn0 = fmaxf(m0, rm0), mn1 = fmaxf(m1, rm1);
        const float sc0 = __expf(m0 - mn0), sc1 = __expf(m1 - mn1);
        float rs0 = 0.f, rs1 = 0.f;
#pragma unroll
        for (int nt = 0; nt < 8; nt++) {
            S[nt][0] = __expf(S[nt][0] - mn0); rs0 += S[nt][0];
            S[nt][1] = __expf(S[nt][1] - mn0); rs0 += S[nt][1];
            S[nt][2] = __expf(S[nt][2] - mn1); rs1 += S[nt][2];
            S[nt][3] = __expf(S[nt][3] - mn1); rs1 += S[nt][3];
        }
        rs0 += __shfl_xor_sync(0xffffffffu, rs0, 1);
        rs0 += __shfl_xor_sync(0xffffffffu, rs0, 2);
        rs1 += __shfl_xor_sync(0xffffffffu, rs1, 1);
        rs1 += __shfl_xor_sync(0xffffffffu, rs1, 2);
        l0 = l0 * sc0 + rs0; l1 = l1 * sc1 + rs1;
        m0 = mn0; m1 = mn1;
#pragma unroll
        for (int nt = 0; nt < 8; nt++) {
            O[nt][0] *= sc0; O[nt][1] *= sc0;
            O[nt][2] *= sc1; O[nt][3] *= sc1;
        }

        // stash diagonal p's for rel-value stencil
        if (window) {
#pragma unroll
            for (int nt = 0; nt < 8; nt++) {
#pragma unroll
                for (int r = 0; r < 4; r++) {
                    const int tlr = wloc + g + ((r >> 1) << 3);
                    const int d = (s0 + nt * 8 + tg * 2 + (r & 1)) - (t0 + tlr);
                    if (d >= -4 && d <= 4) sPd[tlr * 12 + d + 4] = S[nt][r];
                }
            }
        }

        // ---- O += P V ----
#pragma unroll
        for (int ks = 0; ks < 4; ks++) {
            uint32_t aph[4], apl[4];
            pack_pair(S[2 * ks][0],     S[2 * ks][1],     aph[0], apl[0]);
            pack_pair(S[2 * ks][2],     S[2 * ks][3],     aph[1], apl[1]);
            pack_pair(S[2 * ks + 1][0], S[2 * ks + 1][1], aph[2], apl[2]);
            pack_pair(S[2 * ks + 1][2], S[2 * ks + 1][3], aph[3], apl[3]);
#pragma unroll
            for (int nt = 0; nt < 8; nt++) {
                const int vr = (nt * 8 + g) * QSTR + ks * 16 + tg * 2;
                uint32_t bh[2], bl[2];
                bh[0] = ldb32(&sVh[vr]);
                bh[1] = ldb32(&sVh[vr + 8]);
                bl[0] = ldb32(&sVl[vr]);
                bl[1] = ldb32(&sVl[vr + 8]);
                MMA16816(O[nt], aph, bh);
                MMA16816(O[nt], aph, bl);
                MMA16816(O[nt], apl, bh);
            }
        }

        // ---- rel-value 9-tap stencil ----
        if (window) {
            __syncthreads();
#pragma unroll
            for (int rh = 0; rh < 2; rh++) {
                const int tlr = wloc + g + rh * 8;
#pragma unroll
                for (int dd = 0; dd < 9; dd++) {
                    const float p = sPd[tlr * 12 + dd];
                    if (p != 0.f) {
#pragma unroll
                        for (int nt = 0; nt < 8; nt++) {
                            O[nt][2 * rh]     += p * sEV[dd * 64 + nt * 8 + tg * 2];
                            O[nt][2 * rh + 1] += p * sEV[dd * 64 + nt * 8 + tg * 2 + 1];
                        }
                    }
                }
            }
        }
    }

    // ---- finalize: normalize, stage [kc][t] in smem, coalesced store ----
    __syncthreads();
    const float inv0 = 1.f / l0, inv1 = 1.f / l1;
#pragma unroll
    for (int nt = 0; nt < 8; nt++) {
#pragma unroll
        for (int r = 0; r < 4; r++) {
            const int tlr = wloc + g + ((r >> 1) << 3);
            const int kc = nt * 8 + tg * 2 + (r & 1);
            sOut[kc * 132 + tlr] = O[nt][r] * ((r >> 1) ? inv1 : inv0);
        }
    }
    __syncthreads();
    for (int i = tid; i < 8192; i += 256) {
        const int t = i & 127, kc = i >> 7;
        d_A[qbase + (size_t)kc * Tv + t0 + t] = sOut[kc * 132 + t];
    }
}

// ---------------------------------------------------------------------------

extern "C" void kernel_launch(void* const* d_in, const int* in_sizes, int n_in,
                              void* d_out, int out_size)
{
    const float* x    = (const float*)d_in[0];
    const float* c    = (const float*)d_in[1];
    const float* mask = (const float*)d_in[2];
    const float* Wq   = (const float*)d_in[3];
    const float* bq   = (const float*)d_in[4];
    const float* Wk   = (const float*)d_in[5];
    const float* bk   = (const float*)d_in[6];
    const float* Wv   = (const float*)d_in[7];
    const float* bv   = (const float*)d_in[8];
    const float* Wo   = (const float*)d_in[9];
    const float* bo   = (const float*)d_in[10];
    const float* ek   = (const float*)d_in[11];
    const float* ev   = (const float*)d_in[12];
    float* out = (float*)d_out;

    float *Qp, *Kp, *Vp, *Ap;
    __nv_bfloat16 *whi, *wlo, *bhi, *blo, *chi, *clo;
    cudaGetSymbolAddress((void**)&Qp, d_Q);
    cudaGetSymbolAddress((void**)&Kp, d_K);
    cudaGetSymbolAddress((void**)&Vp, d_V);
    cudaGetSymbolAddress((void**)&Ap, d_A);
    cudaGetSymbolAddress((void**)&whi, g_Whi);
    cudaGetSymbolAddress((void**)&wlo, g_Wlo);
    cudaGetSymbolAddress((void**)&bhi, g_Bhi);
    cudaGetSymbolAddress((void**)&blo, g_Blo);
    cudaGetSymbolAddress((void**)&chi, g_Chi);
    cudaGetSymbolAddress((void**)&clo, g_Clo);

    cudaFuncSetAttribute(attn_hmma, cudaFuncAttributeMaxDynamicSharedMemorySize,
                         ATTN_SMEM_BYTES);

    const int WSZ = Cv * Cv;  // 262144

    // weight splits (single launch)
    dim3 wg(WSZ / 256, 4);
    convw4_kernel<<<wg, 256>>>(Wq, Wk, Wv, Wo, whi, wlo);

    // activation transposed splits
    dim3 tg(Tv / 32, Cv / 32, Bv), tb(32, 8);
    tconv_kernel<<<tg, tb>>>(x, bhi, blo);
    tconv_kernel<<<tg, tb>>>(c, chi, clo);

    // projections (Q pre-scaled by 1/sqrt(KC))
    dim3 gg(Tv / 128, Cv / 128, Bv);
    hmma_proj<<<gg, 256>>>(whi + 0 * WSZ, wlo + 0 * WSZ, bhi, blo, bq, Qp, 0.125f);
    hmma_proj<<<gg, 256>>>(whi + 1 * WSZ, wlo + 1 * WSZ, chi, clo, bk, Kp, 1.0f);
    hmma_proj<<<gg, 256>>>(whi + 2 * WSZ, wlo + 2 * WSZ, chi, clo, bv, Vp, 1.0f);

    // attention
    dim3 ga(Tv / 128, Hh, Bv);
    attn_hmma<<<ga, 256, ATTN_SMEM_BYTES>>>(mask, ek, ev);

    // output projection (reuse x's transposed buffers for A)
    tconv_kernel<<<tg, tb>>>(Ap, bhi, blo);
    hmma_proj<<<gg, 256>>>(whi + 3 * WSZ, wlo + 3 * WSZ, bhi, blo, bo, out, 1.0f);
}

// round 8
// speedup vs baseline: 2.0960x; 1.3526x over previous
#include <cuda_runtime.h>
#include <cuda_bf16.h>
#include <math.h>
#include <stdint.h>

#define Bv 8
#define Cv 512
#define Tv 1024
#define Hh 8
#define KCv 64

// ---------------------------------------------------------------------------
// Scratch (allocation-free rule: __device__ globals)
// ---------------------------------------------------------------------------
__device__ __nv_bfloat16 g_Whi[4 * Cv * Cv];
__device__ __nv_bfloat16 g_Wlo[4 * Cv * Cv];
__device__ __nv_bfloat16 g_Xhi[Bv * Tv * Cv];   // x^T split; later attention output
__device__ __nv_bfloat16 g_Xlo[Bv * Tv * Cv];
__device__ __nv_bfloat16 g_Chi[Bv * Tv * Cv];   // c^T split
__device__ __nv_bfloat16 g_Clo[Bv * Tv * Cv];
__device__ __nv_bfloat16 g_Qhi[Bv * Tv * Cv];   // Q split, [b][t][C], pre-scaled
__device__ __nv_bfloat16 g_Qlo[Bv * Tv * Cv];
__device__ __nv_bfloat16 g_Khi[Bv * Tv * Cv];   // K split, [b][t][C]
__device__ __nv_bfloat16 g_Klo[Bv * Tv * Cv];
__device__ __nv_bfloat16 g_Vhi[Bv * Cv * Tv];   // V split, [b][C][t]
__device__ __nv_bfloat16 g_Vlo[Bv * Cv * Tv];
__device__ uint32_t      g_BM[Bv * Tv * 32];    // mask bitmask, bit s of word w: s = w*32+bit

// ---------------------------------------------------------------------------
// mma.sync m16n8k16 bf16 -> f32 (classic HMMA; works on plain sm_103 target)
// ---------------------------------------------------------------------------
#define MMA16816(d, a, b) \
    asm volatile("mma.sync.aligned.m16n8k16.row.col.f32.bf16.bf16.f32 " \
        "{%0,%1,%2,%3}, {%4,%5,%6,%7}, {%8,%9}, {%0,%1,%2,%3};" \
        : "+f"((d)[0]), "+f"((d)[1]), "+f"((d)[2]), "+f"((d)[3]) \
        : "r"((a)[0]), "r"((a)[1]), "r"((a)[2]), "r"((a)[3]), \
          "r"((b)[0]), "r"((b)[1]))

__device__ __forceinline__ uint32_t ldb32(const __nv_bfloat16* p) {
    return *reinterpret_cast<const uint32_t*>(p);
}
__device__ __forceinline__ void pack_pair(float x, float y, uint32_t& hi, uint32_t& lo) {
    const __nv_bfloat16 hx = __float2bfloat16(x), hy = __float2bfloat16(y);
    const __nv_bfloat16 lx = __float2bfloat16(x - __bfloat162float(hx));
    const __nv_bfloat16 ly = __float2bfloat16(y - __bfloat162float(hy));
    __nv_bfloat162 h2; h2.x = hx; h2.y = hy;
    __nv_bfloat162 l2; l2.x = lx; l2.y = ly;
    hi = *reinterpret_cast<const uint32_t*>(&h2);
    lo = *reinterpret_cast<const uint32_t*>(&l2);
}

// ---------------------------------------------------------------------------
// fp32 -> (hi, lo) bf16 split for 4 weight matrices in one launch
// ---------------------------------------------------------------------------
__global__ __launch_bounds__(256) void convw4_kernel(
    const float* __restrict__ w0, const float* __restrict__ w1,
    const float* __restrict__ w2, const float* __restrict__ w3)
{
    const int m = blockIdx.y;
    const float* w = (m == 0) ? w0 : (m == 1) ? w1 : (m == 2) ? w2 : w3;
    const int i = blockIdx.x * 256 + threadIdx.x;
    const float v = w[i];
    const __nv_bfloat16 h = __float2bfloat16(v);
    g_Whi[m * Cv * Cv + i] = h;
    g_Wlo[m * Cv * Cv + i] = __float2bfloat16(v - __bfloat162float(h));
}

// ---------------------------------------------------------------------------
// [b][c][t] fp32 -> [b][t][c] bf16 hi/lo (transpose + split)
// grid (T/32, C/32, B), block (32, 8)
// ---------------------------------------------------------------------------
__global__ __launch_bounds__(256) void tconv_kernel(
    const float* __restrict__ in, __nv_bfloat16* __restrict__ hi, __nv_bfloat16* __restrict__ lo)
{
    __shared__ float tile[32][33];
    const int b = blockIdx.z, c0 = blockIdx.y * 32, t0 = blockIdx.x * 32;
    const int tx = threadIdx.x, ty = threadIdx.y;
    const float* src = in + ((size_t)b * Cv + c0) * Tv + t0;
#pragma unroll
    for (int i = ty; i < 32; i += 8)
        tile[i][tx] = src[(size_t)i * Tv + tx];
    __syncthreads();
#pragma unroll
    for (int i = ty; i < 32; i += 8) {
        const float v = tile[tx][i];
        const size_t o = ((size_t)b * Tv + t0 + i) * Cv + c0 + tx;
        const __nv_bfloat16 h = __float2bfloat16(v);
        hi[o] = h;
        lo[o] = __float2bfloat16(v - __bfloat162float(h));
    }
}

// ---------------------------------------------------------------------------
// mask -> bitmask: g_BM[(b*T + t)*32 + w] bit i = (mask[b][t][w*32+i] != 0)
// grid (T/8, B), block 256 (8 warps; warp = one t row)
// ---------------------------------------------------------------------------
__global__ __launch_bounds__(256) void maskbits_kernel(const float* __restrict__ mask)
{
    const int b = blockIdx.y;
    const int t = blockIdx.x * 8 + (threadIdx.x >> 5);
    const int lane = threadIdx.x & 31;
    const float* row = mask + ((size_t)b * Tv + t) * Tv;
    uint32_t* dst = g_BM + ((size_t)b * Tv + t) * 32;
#pragma unroll 4
    for (int wd = 0; wd < 32; wd++) {
        const float v = row[wd * 32 + lane];
        const uint32_t word = __ballot_sync(0xffffffffu, v != 0.f);
        if (lane == 0) dst[wd] = word;
    }
}

// ---------------------------------------------------------------------------
// HMMA split-bf16 GEMM with register-prefetch pipeline.
// MODE 0: D[t][o] = act[t][:] . W[o][:]^T; out split bf16 [b][t][C] (Q/K)
// MODE 1: D[o][t] = W[o][:] . act[t][:]^T; out split bf16 [b][C][t] (V)
// MODE 2: D[o][t] ... out fp32 [b][C][t] (final projection)
// grid: MODE0 (C/128, T/128, B); MODE1/2 (T/128, C/128, B). block 256.
// D = Ah*Bh + Ah*Bl + Al*Bh, fp32 accumulators. value = (acc + bias[o]) * scale.
// ---------------------------------------------------------------------------
#define KCH 32
#define SSTR 40

template<int MODE>
__global__ __launch_bounds__(256) void hmma_gemm(
    const __nv_bfloat16* __restrict__ Wh_, const __nv_bfloat16* __restrict__ Wl_,
    const __nv_bfloat16* __restrict__ Acth, const __nv_bfloat16* __restrict__ Actl,
    const float* __restrict__ bias, float scale,
    float* __restrict__ outf,
    __nv_bfloat16* __restrict__ outhi, __nv_bfloat16* __restrict__ outlo)
{
    __shared__ __nv_bfloat16 sAh[128 * SSTR];
    __shared__ __nv_bfloat16 sAl[128 * SSTR];
    __shared__ __nv_bfloat16 sBh[128 * SSTR];
    __shared__ __nv_bfloat16 sBl[128 * SSTR];

    const int nblk = blockIdx.x * 128, mblk = blockIdx.y * 128, b = blockIdx.z;
    const int tid = threadIdx.x, wid = tid >> 5, lid = tid & 31;
    const int wm = wid >> 2, wn = wid & 3;
    const int m0 = wm * 64, n0 = wn * 32;
    const int g = lid >> 2, tg = lid & 3;

    const __nv_bfloat16 *pAh, *pAl, *pBh, *pBl;
    if (MODE == 0) {
        pAh = Acth + ((size_t)b * Tv + mblk) * Cv;
        pAl = Actl + ((size_t)b * Tv + mblk) * Cv;
        pBh = Wh_ + (size_t)nblk * Cv;
        pBl = Wl_ + (size_t)nblk * Cv;
    } else {
        pAh = Wh_ + (size_t)mblk * Cv;
        pAl = Wl_ + (size_t)mblk * Cv;
        pBh = Acth + ((size_t)b * Tv + nblk) * Cv;
        pBl = Actl + ((size_t)b * Tv + nblk) * Cv;
    }

    float acc[4][4][4];
#pragma unroll
    for (int mi = 0; mi < 4; mi++)
#pragma unroll
        for (int nj = 0; nj < 4; nj++)
#pragma unroll
            for (int r = 0; r < 4; r++) acc[mi][nj][r] = 0.f;

    uint4 ra_h[2], ra_l[2], rb_h[2], rb_l[2];
#pragma unroll
    for (int u = 0; u < 2; u++) {
        const int idx = tid + u * 256;
        const int r = idx >> 2, c8 = (idx & 3) * 8;
        ra_h[u] = *reinterpret_cast<const uint4*>(&pAh[(size_t)r * Cv + c8]);
        ra_l[u] = *reinterpret_cast<const uint4*>(&pAl[(size_t)r * Cv + c8]);
        rb_h[u] = *reinterpret_cast<const uint4*>(&pBh[(size_t)r * Cv + c8]);
        rb_l[u] = *reinterpret_cast<const uint4*>(&pBl[(size_t)r * Cv + c8]);
    }

    for (int kc0 = 0; kc0 < Cv; kc0 += KCH) {
        __syncthreads();
#pragma unroll
        for (int u = 0; u < 2; u++) {
            const int idx = tid + u * 256;
            const int r = idx >> 2, c8 = (idx & 3) * 8;
            *reinterpret_cast<uint4*>(&sAh[r * SSTR + c8]) = ra_h[u];
            *reinterpret_cast<uint4*>(&sAl[r * SSTR + c8]) = ra_l[u];
            *reinterpret_cast<uint4*>(&sBh[r * SSTR + c8]) = rb_h[u];
            *reinterpret_cast<uint4*>(&sBl[r * SSTR + c8]) = rb_l[u];
        }
        __syncthreads();
        if (kc0 + KCH < Cv) {
            const int kn = kc0 + KCH;
#pragma unroll
            for (int u = 0; u < 2; u++) {
                const int idx = tid + u * 256;
                const int r = idx >> 2, c8 = (idx & 3) * 8;
                ra_h[u] = *reinterpret_cast<const uint4*>(&pAh[(size_t)r * Cv + kn + c8]);
                ra_l[u] = *reinterpret_cast<const uint4*>(&pAl[(size_t)r * Cv + kn + c8]);
                rb_h[u] = *reinterpret_cast<const uint4*>(&pBh[(size_t)r * Cv + kn + c8]);
                rb_l[u] = *reinterpret_cast<const uint4*>(&pBl[(size_t)r * Cv + kn + c8]);
            }
        }

#pragma unroll
        for (int ks = 0; ks < KCH; ks += 16) {
            const int kk = ks + tg * 2;
            uint32_t ah[4][4], al[4][4], bh[4][2], bl[4][2];
#pragma unroll
            for (int mi = 0; mi < 4; mi++) {
                const int row = m0 + mi * 16 + g;
                ah[mi][0] = ldb32(&sAh[row * SSTR + kk]);
                ah[mi][1] = ldb32(&sAh[(row + 8) * SSTR + kk]);
                ah[mi][2] = ldb32(&sAh[row * SSTR + kk + 8]);
                ah[mi][3] = ldb32(&sAh[(row + 8) * SSTR + kk + 8]);
                al[mi][0] = ldb32(&sAl[row * SSTR + kk]);
                al[mi][1] = ldb32(&sAl[(row + 8) * SSTR + kk]);
                al[mi][2] = ldb32(&sAl[row * SSTR + kk + 8]);
                al[mi][3] = ldb32(&sAl[(row + 8) * SSTR + kk + 8]);
            }
#pragma unroll
            for (int nj = 0; nj < 4; nj++) {
                const int col = n0 + nj * 8 + g;
                bh[nj][0] = ldb32(&sBh[col * SSTR + kk]);
                bh[nj][1] = ldb32(&sBh[col * SSTR + kk + 8]);
                bl[nj][0] = ldb32(&sBl[col * SSTR + kk]);
                bl[nj][1] = ldb32(&sBl[col * SSTR + kk + 8]);
            }
#pragma unroll
            for (int mi = 0; mi < 4; mi++)
#pragma unroll
                for (int nj = 0; nj < 4; nj++) {
                    MMA16816(acc[mi][nj], ah[mi], bh[nj]);
                    MMA16816(acc[mi][nj], ah[mi], bl[nj]);
                    MMA16816(acc[mi][nj], al[mi], bh[nj]);
                }
        }
    }

    // ---- epilogues ----
    if (MODE == 0) {
        // rows m = t, cols n = o; pairs along o -> word at [b][t][o]
#pragma unroll
        for (int mi = 0; mi < 4; mi++) {
            const int t0r = mblk + m0 + mi * 16 + g;
#pragma unroll
            for (int nj = 0; nj < 4; nj++) {
                const int o = nblk + n0 + nj * 8 + tg * 2;
                const float b0 = bias[o], b1 = bias[o + 1];
                uint32_t hw, lw;
                pack_pair((acc[mi][nj][0] + b0) * scale, (acc[mi][nj][1] + b1) * scale, hw, lw);
                const size_t a0 = ((size_t)b * Tv + t0r) * Cv + o;
                *reinterpret_cast<uint32_t*>(&outhi[a0]) = hw;
                *reinterpret_cast<uint32_t*>(&outlo[a0]) = lw;
                pack_pair((acc[mi][nj][2] + b0) * scale, (acc[mi][nj][3] + b1) * scale, hw, lw);
                const size_t a1 = ((size_t)b * Tv + t0r + 8) * Cv + o;
                *reinterpret_cast<uint32_t*>(&outhi[a1]) = hw;
                *reinterpret_cast<uint32_t*>(&outlo[a1]) = lw;
            }
        }
    } else if (MODE == 1) {
        // rows m = o, cols n = t; pairs along t -> word at [b][o][t]
#pragma unroll
        for (int mi = 0; mi < 4; mi++) {
            const int o = mblk + m0 + mi * 16 + g;
            const float b0 = bias[o], b1 = bias[o + 8];
#pragma unroll
            for (int nj = 0; nj < 4; nj++) {
                const int t = nblk + n0 + nj * 8 + tg * 2;
                uint32_t hw, lw;
                pack_pair((acc[mi][nj][0] + b0) * scale, (acc[mi][nj][1] + b0) * scale, hw, lw);
                const size_t a0 = ((size_t)b * Cv + o) * Tv + t;
                *reinterpret_cast<uint32_t*>(&outhi[a0]) = hw;
                *reinterpret_cast<uint32_t*>(&outlo[a0]) = lw;
                pack_pair((acc[mi][nj][2] + b1) * scale, (acc[mi][nj][3] + b1) * scale, hw, lw);
                const size_t a1 = ((size_t)b * Cv + o + 8) * Tv + t;
                *reinterpret_cast<uint32_t*>(&outhi[a1]) = hw;
                *reinterpret_cast<uint32_t*>(&outlo[a1]) = lw;
            }
        }
    } else {
#pragma unroll
        for (int mi = 0; mi < 4; mi++) {
            const int o = mblk + m0 + mi * 16 + g;
            const float b0 = bias[o], b1 = bias[o + 8];
#pragma unroll
            for (int nj = 0; nj < 4; nj++) {
                const int t = nblk + n0 + nj * 8 + tg * 2;
                float2 v0, v1;
                v0.x = (acc[mi][nj][0] + b0) * scale;
                v0.y = (acc[mi][nj][1] + b0) * scale;
                v1.x = (acc[mi][nj][2] + b1) * scale;
                v1.y = (acc[mi][nj][3] + b1) * scale;
                *reinterpret_cast<float2*>(&outf[((size_t)b * Cv + o) * Tv + t]) = v0;
                *reinterpret_cast<float2*>(&outf[((size_t)b * Cv + o + 8) * Tv + t]) = v1;
            }
        }
    }
}

// ---------------------------------------------------------------------------
// HMMA banded flash attention, split-bf16 inputs pre-staged in global memory.
// grid (T/128, H, B), block 256 (8 warps x 16 rows). Q pre-scaled.
// Output written split-bf16 to g_Xhi/g_Xlo [b][t][C].
// ---------------------------------------------------------------------------
#define QSTR 72

#define OFF_QH 0
#define OFF_QL (128 * QSTR)
#define OFF_KH (2 * 128 * QSTR)
#define OFF_KL (2 * 128 * QSTR + 64 * QSTR)
#define OFF_VH (2 * 128 * QSTR + 2 * 64 * QSTR)
#define OFF_VL (2 * 128 * QSTR + 3 * 64 * QSTR)
#define BF16_ELEMS (2 * 128 * QSTR + 4 * 64 * QSTR)
#define F_RK   0
#define F_BIAS (128 * 12)
#define F_EV   (128 * 12 + 516)
#define F_EK   (128 * 12 + 516 + 576)
#define F_PD   (128 * 12 + 516 + 2 * 576)
#define F_TOTAL (2 * 128 * 12 + 516 + 2 * 576)
#define ATTN_SMEM_BYTES (BF16_ELEMS * 2 + F_TOTAL * 4)

__global__ __launch_bounds__(256, 1) void attn_hmma(
    const float* __restrict__ ek, const float* __restrict__ ev)
{
    extern __shared__ __align__(16) char smem_raw[];
    __nv_bfloat16* sB16 = reinterpret_cast<__nv_bfloat16*>(smem_raw);
    float* sF = reinterpret_cast<float*>(smem_raw + BF16_ELEMS * 2);
    __nv_bfloat16* sQh = sB16 + OFF_QH;
    __nv_bfloat16* sQl = sB16 + OFF_QL;
    __nv_bfloat16* sKh = sB16 + OFF_KH;
    __nv_bfloat16* sKl = sB16 + OFF_KL;
    __nv_bfloat16* sVh = sB16 + OFF_VH;
    __nv_bfloat16* sVl = sB16 + OFF_VL;
    float* sRK   = sF + F_RK;
    float* sBias = sF + F_BIAS;
    float* sEV   = sF + F_EV;
    float* sEK   = sF + F_EK;
    float* sPd   = sF + F_PD;

    const int t0 = blockIdx.x * 128;
    const int h  = blockIdx.y;
    const int b  = blockIdx.z;
    const int tid = threadIdx.x, wid = tid >> 5, lid = tid & 31;
    const int g = lid >> 2, tg = lid & 3;
    const int wloc = wid * 16;

    // base pointers (row index = absolute t / s; no negative offsets)
    const __nv_bfloat16* Kh_b = g_Khi + ((size_t)b * Tv) * Cv + h * 64;
    const __nv_bfloat16* Kl_b = g_Klo + ((size_t)b * Tv) * Cv + h * 64;
    const __nv_bfloat16* Vh_b = g_Vhi + ((size_t)b * Cv + h * 64) * Tv;
    const __nv_bfloat16* Vl_b = g_Vlo + ((size_t)b * Cv + h * 64) * Tv;
    const size_t qrow0 = ((size_t)b * Tv + t0) * Cv + h * 64;

    // Load Q: 128 rows x 64 kc = 1024 uint4 per array
    for (int i = tid; i < 1024; i += 256) {
        const int t = i >> 3, seg = (i & 7) * 8;
        *reinterpret_cast<uint4*>(&sQh[t * QSTR + seg]) =
            *reinterpret_cast<const uint4*>(&g_Qhi[qrow0 + (size_t)t * Cv + seg]);
        *reinterpret_cast<uint4*>(&sQl[t * QSTR + seg]) =
            *reinterpret_cast<const uint4*>(&g_Qlo[qrow0 + (size_t)t * Cv + seg]);
    }
    for (int i = tid; i < 513; i += 256)
        sBias[i] = -log1pf(fabsf((float)(i - 256)));
    for (int i = tid; i < 576; i += 256) { sEK[i] = ek[i]; sEV[i] = ev[i]; }
    __syncthreads();

    // sRK[t][d] = sum_kc q[t][kc] * ek[d][kc]
    for (int i = tid; i < 1152; i += 256) {
        const int tl = i & 127, dd = i >> 7;
        float s = 0.f;
#pragma unroll 16
        for (int kc = 0; kc < 64; kc++) {
            const float q = __bfloat162float(sQh[tl * QSTR + kc]) +
                            __bfloat162float(sQl[tl * QSTR + kc]);
            s += q * sEK[dd * 64 + kc];
        }
        sRK[tl * 12 + dd] = s;
    }

    float m0 = -1e30f, m1 = -1e30f, l0 = 0.f, l1 = 0.f;
    float O[8][4];
#pragma unroll
    for (int nt = 0; nt < 8; nt++)
#pragma unroll
        for (int r = 0; r < 4; r++) O[nt][r] = 0.f;

    const int s_lo = max(0, t0 - 256);
    const int s_hi = min(Tv, t0 + 128 + 256);

    // K/V chunk prefetch: 64 rows x 64 cols = 512 uint4 per array -> 2 per thread
    uint4 kh[2], kl[2], vh[2], vl[2];
#pragma unroll
    for (int u = 0; u < 2; u++) {
        const int idx = tid + u * 256;
        const int fr = idx >> 3, fseg = (idx & 7) * 8;
        kh[u] = *reinterpret_cast<const uint4*>(&Kh_b[(size_t)(s_lo + fr) * Cv + fseg]);
        kl[u] = *reinterpret_cast<const uint4*>(&Kl_b[(size_t)(s_lo + fr) * Cv + fseg]);
        vh[u] = *reinterpret_cast<const uint4*>(&Vh_b[(size_t)fr * Tv + s_lo + fseg]);
        vl[u] = *reinterpret_cast<const uint4*>(&Vl_b[(size_t)fr * Tv + s_lo + fseg]);
    }

    for (int s0 = s_lo; s0 < s_hi; s0 += 64) {
        const bool window = (s0 >= t0 - 64) && (s0 <= t0 + 128);
        __syncthreads();
        if (window) {
            for (int i = tid; i < 1536; i += 256) sPd[i] = 0.f;
        }
#pragma unroll
        for (int u = 0; u < 2; u++) {
            const int idx = tid + u * 256;
            const int fr = idx >> 3, fseg = (idx & 7) * 8;
            *reinterpret_cast<uint4*>(&sKh[fr * QSTR + fseg]) = kh[u];
            *reinterpret_cast<uint4*>(&sKl[fr * QSTR + fseg]) = kl[u];
            *reinterpret_cast<uint4*>(&sVh[fr * QSTR + fseg]) = vh[u];
            *reinterpret_cast<uint4*>(&sVl[fr * QSTR + fseg]) = vl[u];
        }
        __syncthreads();
        if (s0 + 64 < s_hi) {
            const int sn = s0 + 64;
#pragma unroll
            for (int u = 0; u < 2; u++) {
                const int idx = tid + u * 256;
                const int fr = idx >> 3, fseg = (idx & 7) * 8;
                kh[u] = *reinterpret_cast<const uint4*>(&Kh_b[(size_t)(sn + fr) * Cv + fseg]);
                kl[u] = *reinterpret_cast<const uint4*>(&Kl_b[(size_t)(sn + fr) * Cv + fseg]);
                vh[u] = *reinterpret_cast<const uint4*>(&Vh_b[(size_t)fr * Tv + sn + fseg]);
                vl[u] = *reinterpret_cast<const uint4*>(&Vl_b[(size_t)fr * Tv + sn + fseg]);
            }
        }

        // mask bitmask words for this thread's two rows
        const int w0 = s0 >> 5;
        const int row0 = t0 + wloc + g;
        const uint32_t bA0 = g_BM[((size_t)b * Tv + row0) * 32 + w0];
        const uint32_t bA1 = g_BM[((size_t)b * Tv + row0) * 32 + w0 + 1];
        const uint32_t bB0 = g_BM[((size_t)b * Tv + row0 + 8) * 32 + w0];
        const uint32_t bB1 = g_BM[((size_t)b * Tv + row0 + 8) * 32 + w0 + 1];

        // ---- S = Q K^T ----
        float S[8][4];
#pragma unroll
        for (int nt = 0; nt < 8; nt++)
#pragma unroll
            for (int r = 0; r < 4; r++) S[nt][r] = 0.f;

#pragma unroll
        for (int ks = 0; ks < 4; ks++) {
            const int qr = (wloc + g) * QSTR + ks * 16 + tg * 2;
            uint32_t aqh[4], aql[4];
            aqh[0] = ldb32(&sQh[qr]);
            aqh[1] = ldb32(&sQh[qr + 8 * QSTR]);
            aqh[2] = ldb32(&sQh[qr + 8]);
            aqh[3] = ldb32(&sQh[qr + 8 * QSTR + 8]);
            aql[0] = ldb32(&sQl[qr]);
            aql[1] = ldb32(&sQl[qr + 8 * QSTR]);
            aql[2] = ldb32(&sQl[qr + 8]);
            aql[3] = ldb32(&sQl[qr + 8 * QSTR + 8]);
#pragma unroll
            for (int nt = 0; nt < 8; nt++) {
                const int kr = (nt * 8 + g) * QSTR + ks * 16 + tg * 2;
                uint32_t bh[2], bl[2];
                bh[0] = ldb32(&sKh[kr]);
                bh[1] = ldb32(&sKh[kr + 8]);
                bl[0] = ldb32(&sKl[kr]);
                bl[1] = ldb32(&sKl[kr + 8]);
                MMA16816(S[nt], aqh, bh);
                MMA16816(S[nt], aqh, bl);
                MMA16816(S[nt], aql, bh);
            }
        }

        // ---- biases + band + mask ----
#pragma unroll
        for (int nt = 0; nt < 8; nt++) {
#pragma unroll
            for (int r = 0; r < 4; r++) {
                const int tlr = wloc + g + ((r >> 1) << 3);
                const int t = t0 + tlr;
                const int si = nt * 8 + tg * 2 + (r & 1);
                const int s = s0 + si;
                const int d = s - t;
                float v = S[nt][r];
                if (d >= -256 && d <= 256) {
                    v += sBias[d + 256];
                    if (d >= -4 && d <= 4) v += sRK[tlr * 12 + d + 4];
                    const uint32_t wv = (r >> 1) ? ((si >= 32) ? bB1 : bB0)
                                                 : ((si >= 32) ? bA1 : bA0);
                    if (!((wv >> (si & 31)) & 1u)) v = -1e4f;
                } else {
                    v = -2e30f;
                }
                S[nt][r] = v;
            }
        }

        // ---- online softmax ----
        float rm0 = -2e30f, rm1 = -2e30f;
#pragma unroll
        for (int nt = 0; nt < 8; nt++) {
            rm0 = fmaxf(rm0, fmaxf(S[nt][0], S[nt][1]));
            rm1 = fmaxf(rm1, fmaxf(S[nt][2], S[nt][3]));
        }
        rm0 = fmaxf(rm0, __shfl_xor_sync(0xffffffffu, rm0, 1));
        rm0 = fmaxf(rm0, __shfl_xor_sync(0xffffffffu, rm0, 2));
        rm1 = fmaxf(rm1, __shfl_xor_sync(0xffffffffu, rm1, 1));
        rm1 = fmaxf(rm1, __shfl_xor_sync(0xffffffffu, rm1, 2));
        const float mn0 = fmaxf(m0, rm0), mn1 = fmaxf(m1, rm1);
        const float sc0 = __expf(m0 - mn0), sc1 = __expf(m1 - mn1);
        float rs0 = 0.f, rs1 = 0.f;
#pragma unroll
        for (int nt = 0; nt < 8; nt++) {
            S[nt][0] = __expf(S[nt][0] - mn0); rs0 += S[nt][0];
            S[nt][1] = __expf(S[nt][1] - mn0); rs0 += S[nt][1];
            S[nt][2] = __expf(S[nt][2] - mn1); rs1 += S[nt][2];
            S[nt][3] = __expf(S[nt][3] - mn1); rs1 += S[nt][3];
        }
        rs0 += __shfl_xor_sync(0xffffffffu, rs0, 1);
        rs0 += __shfl_xor_sync(0xffffffffu, rs0, 2);
        rs1 += __shfl_xor_sync(0xffffffffu, rs1, 1);
        rs1 += __shfl_xor_sync(0xffffffffu, rs1, 2);
        l0 = l0 * sc0 + rs0; l1 = l1 * sc1 + rs1;
        m0 = mn0; m1 = mn1;
#pragma unroll
        for (int nt = 0; nt < 8; nt++) {
            O[nt][0] *= sc0; O[nt][1] *= sc0;
            O[nt][2] *= sc1; O[nt][3] *= sc1;
        }

        // stash diagonal p's for rel-value stencil
        if (window) {
#pragma unroll
            for (int nt = 0; nt < 8; nt++) {
#pragma unroll
                for (int r = 0; r < 4; r++) {
                    const int tlr = wloc + g + ((r >> 1) << 3);
                    const int d = (s0 + nt * 8 + tg * 2 + (r & 1)) - (t0 + tlr);
                    if (d >= -4 && d <= 4) sPd[tlr * 12 + d + 4] = S[nt][r];
                }
            }
        }

        // ---- O += P V ----
#pragma unroll
        for (int ks = 0; ks < 4; ks++) {
            uint32_t aph[4], apl[4];
            pack_pair(S[2 * ks][0],     S[2 * ks][1],     aph[0], apl[0]);
            pack_pair(S[2 * ks][2],     S[2 * ks][3],     aph[1], apl[1]);
            pack_pair(S[2 * ks + 1][0], S[2 * ks + 1][1], aph[2], apl[2]);
            pack_pair(S[2 * ks + 1][2], S[2 * ks + 1][3], aph[3], apl[3]);
#pragma unroll
            for (int nt = 0; nt < 8; nt++) {
                const int vr = (nt * 8 + g) * QSTR + ks * 16 + tg * 2;
                uint32_t bh[2], bl[2];
                bh[0] = ldb32(&sVh[vr]);
                bh[1] = ldb32(&sVh[vr + 8]);
                bl[0] = ldb32(&sVl[vr]);
                bl[1] = ldb32(&sVl[vr + 8]);
                MMA16816(O[nt], aph, bh);
                MMA16816(O[nt], aph, bl);
                MMA16816(O[nt], apl, bh);
            }
        }

        // ---- rel-value 9-tap stencil ----
        if (window) {
            __syncthreads();
#pragma unroll
            for (int rh = 0; rh < 2; rh++) {
                const int tlr = wloc + g + rh * 8;
#pragma unroll
                for (int dd = 0; dd < 9; dd++) {
                    const float p = sPd[tlr * 12 + dd];
                    if (p != 0.f) {
#pragma unroll
                        for (int nt = 0; nt < 8; nt++) {
                            O[nt][2 * rh]     += p * sEV[dd * 64 + nt * 8 + tg * 2];
                            O[nt][2 * rh + 1] += p * sEV[dd * 64 + nt * 8 + tg * 2 + 1];
                        }
                    }
                }
            }
        }
    }

    // ---- finalize: normalize + direct split-bf16 store to g_X [b][t][C] ----
    const float inv0 = 1.f / l0, inv1 = 1.f / l1;
    const size_t out0 = ((size_t)b * Tv + t0 + wloc + g) * Cv + h * 64;
    const size_t out1 = out0 + 8 * Cv;
#pragma unroll
    for (int nt = 0; nt < 8; nt++) {
        const int kc = nt * 8 + tg * 2;
        uint32_t hw, lw;
        pack_pair(O[nt][0] * inv0, O[nt][1] * inv0, hw, lw);
        *reinterpret_cast<uint32_t*>(&g_Xhi[out0 + kc]) = hw;
        *reinterpret_cast<uint32_t*>(&g_Xlo[out0 + kc]) = lw;
        pack_pair(O[nt][2] * inv1, O[nt][3] * inv1, hw, lw);
        *reinterpret_cast<uint32_t*>(&g_Xhi[out1 + kc]) = hw;
        *reinterpret_cast<uint32_t*>(&g_Xlo[out1 + kc]) = lw;
    }
}

// ---------------------------------------------------------------------------

extern "C" void kernel_launch(void* const* d_in, const int* in_sizes, int n_in,
                              void* d_out, int out_size)
{
    const float* x    = (const float*)d_in[0];
    const float* c    = (const float*)d_in[1];
    const float* mask = (const float*)d_in[2];
    const float* Wq   = (const float*)d_in[3];
    const float* bq   = (const float*)d_in[4];
    const float* Wk   = (const float*)d_in[5];
    const float* bk   = (const float*)d_in[6];
    const float* Wv   = (const float*)d_in[7];
    const float* bv   = (const float*)d_in[8];
    const float* Wo   = (const float*)d_in[9];
    const float* bo   = (const float*)d_in[10];
    const float* ek   = (const float*)d_in[11];
    const float* ev   = (const float*)d_in[12];
    float* out = (float*)d_out;

    __nv_bfloat16 *whi, *wlo, *xhi, *xlo, *chi, *clo, *qhi, *qlo, *khi, *klo, *vhi, *vlo;
    cudaGetSymbolAddress((void**)&whi, g_Whi);
    cudaGetSymbolAddress((void**)&wlo, g_Wlo);
    cudaGetSymbolAddress((void**)&xhi, g_Xhi);
    cudaGetSymbolAddress((void**)&xlo, g_Xlo);
    cudaGetSymbolAddress((void**)&chi, g_Chi);
    cudaGetSymbolAddress((void**)&clo, g_Clo);
    cudaGetSymbolAddress((void**)&qhi, g_Qhi);
    cudaGetSymbolAddress((void**)&qlo, g_Qlo);
    cudaGetSymbolAddress((void**)&khi, g_Khi);
    cudaGetSymbolAddress((void**)&klo, g_Klo);
    cudaGetSymbolAddress((void**)&vhi, g_Vhi);
    cudaGetSymbolAddress((void**)&vlo, g_Vlo);

    cudaFuncSetAttribute(attn_hmma, cudaFuncAttributeMaxDynamicSharedMemorySize,
                         ATTN_SMEM_BYTES);

    const int WSZ = Cv * Cv;

    // pre-passes
    dim3 wg(WSZ / 256, 4);
    convw4_kernel<<<wg, 256>>>(Wq, Wk, Wv, Wo);
    dim3 tg(Tv / 32, Cv / 32, Bv), tb(32, 8);
    tconv_kernel<<<tg, tb>>>(x, xhi, xlo);
    tconv_kernel<<<tg, tb>>>(c, chi, clo);
    maskbits_kernel<<<dim3(Tv / 8, Bv), 256>>>(mask);

    // projections: Q/K transposed split outputs, V split [C][t]
    hmma_gemm<0><<<dim3(Cv / 128, Tv / 128, Bv), 256>>>(
        whi + 0 * WSZ, wlo + 0 * WSZ, xhi, xlo, bq, 0.125f, nullptr, qhi, qlo);
    hmma_gemm<0><<<dim3(Cv / 128, Tv / 128, Bv), 256>>>(
        whi + 1 * WSZ, wlo + 1 * WSZ, chi, clo, bk, 1.0f, nullptr, khi, klo);
    hmma_gemm<1><<<dim3(Tv / 128, Cv / 128, Bv), 256>>>(
        whi + 2 * WSZ, wlo + 2 * WSZ, chi, clo, bv, 1.0f, nullptr, vhi, vlo);

    // attention (writes split output into g_Xhi/g_Xlo)
    attn_hmma<<<dim3(Tv / 128, Hh, Bv), 256, ATTN_SMEM_BYTES>>>(ek, ev);

    // final projection (fp32 output)
    hmma_gemm<2><<<dim3(Tv / 128, Cv / 128, Bv), 256>>>(
        whi + 3 * WSZ, wlo + 3 * WSZ, xhi, xlo, bo, 1.0f, out, nullptr, nullptr);
}

// round 9
// speedup vs baseline: 2.2095x; 1.0542x over previous
#include <cuda_runtime.h>
#include <cuda_bf16.h>
#include <math.h>
#include <stdint.h>

#define Bv 8
#define Cv 512
#define Tv 1024
#define Hh 8
#define KCv 64

// ---------------------------------------------------------------------------
// Scratch (allocation-free rule: __device__ globals)
// ---------------------------------------------------------------------------
__device__ __nv_bfloat16 g_Whi[4 * Cv * Cv];
__device__ __nv_bfloat16 g_Wlo[4 * Cv * Cv];
__device__ __nv_bfloat16 g_Xhi[Bv * Tv * Cv];   // x^T split; later attention output
__device__ __nv_bfloat16 g_Xlo[Bv * Tv * Cv];
__device__ __nv_bfloat16 g_Chi[Bv * Tv * Cv];   // c^T split
__device__ __nv_bfloat16 g_Clo[Bv * Tv * Cv];
__device__ __nv_bfloat16 g_Qhi[Bv * Tv * Cv];   // Q split, [b][t][C], pre-scaled
__device__ __nv_bfloat16 g_Qlo[Bv * Tv * Cv];
__device__ __nv_bfloat16 g_Khi[Bv * Tv * Cv];   // K split, [b][t][C]
__device__ __nv_bfloat16 g_Klo[Bv * Tv * Cv];
__device__ __nv_bfloat16 g_Vhi[Bv * Cv * Tv];   // V split, [b][C][t]
__device__ __nv_bfloat16 g_Vlo[Bv * Cv * Tv];
__device__ uint32_t      g_BM[Bv * Tv * 32];    // mask bitmask, bit s of word w: s = w*32+bit

// ---------------------------------------------------------------------------
// mma.sync m16n8k16 bf16 -> f32 (classic HMMA; works on plain sm_103 target)
// ---------------------------------------------------------------------------
#define MMA16816(d, a, b) \
    asm volatile("mma.sync.aligned.m16n8k16.row.col.f32.bf16.bf16.f32 " \
        "{%0,%1,%2,%3}, {%4,%5,%6,%7}, {%8,%9}, {%0,%1,%2,%3};" \
        : "+f"((d)[0]), "+f"((d)[1]), "+f"((d)[2]), "+f"((d)[3]) \
        : "r"((a)[0]), "r"((a)[1]), "r"((a)[2]), "r"((a)[3]), \
          "r"((b)[0]), "r"((b)[1]))

__device__ __forceinline__ uint32_t ldb32(const __nv_bfloat16* p) {
    return *reinterpret_cast<const uint32_t*>(p);
}
__device__ __forceinline__ void pack_pair(float x, float y, uint32_t& hi, uint32_t& lo) {
    const __nv_bfloat16 hx = __float2bfloat16(x), hy = __float2bfloat16(y);
    const __nv_bfloat16 lx = __float2bfloat16(x - __bfloat162float(hx));
    const __nv_bfloat16 ly = __float2bfloat16(y - __bfloat162float(hy));
    __nv_bfloat162 h2; h2.x = hx; h2.y = hy;
    __nv_bfloat162 l2; l2.x = lx; l2.y = ly;
    hi = *reinterpret_cast<const uint32_t*>(&h2);
    lo = *reinterpret_cast<const uint32_t*>(&l2);
}

// ---------------------------------------------------------------------------
// fp32 -> (hi, lo) bf16 split for 4 weight matrices in one launch
// ---------------------------------------------------------------------------
__global__ __launch_bounds__(256) void convw4_kernel(
    const float* __restrict__ w0, const float* __restrict__ w1,
    const float* __restrict__ w2, const float* __restrict__ w3)
{
    const int m = blockIdx.y;
    const float* w = (m == 0) ? w0 : (m == 1) ? w1 : (m == 2) ? w2 : w3;
    const int i = blockIdx.x * 256 + threadIdx.x;
    const float v = w[i];
    const __nv_bfloat16 h = __float2bfloat16(v);
    g_Whi[m * Cv * Cv + i] = h;
    g_Wlo[m * Cv * Cv + i] = __float2bfloat16(v - __bfloat162float(h));
}

// ---------------------------------------------------------------------------
// [b][c][t] fp32 -> [b][t][c] bf16 hi/lo (transpose + split)
// grid (T/32, C/32, B), block (32, 8)
// ---------------------------------------------------------------------------
__global__ __launch_bounds__(256) void tconv_kernel(
    const float* __restrict__ in, __nv_bfloat16* __restrict__ hi, __nv_bfloat16* __restrict__ lo)
{
    __shared__ float tile[32][33];
    const int b = blockIdx.z, c0 = blockIdx.y * 32, t0 = blockIdx.x * 32;
    const int tx = threadIdx.x, ty = threadIdx.y;
    const float* src = in + ((size_t)b * Cv + c0) * Tv + t0;
#pragma unroll
    for (int i = ty; i < 32; i += 8)
        tile[i][tx] = src[(size_t)i * Tv + tx];
    __syncthreads();
#pragma unroll
    for (int i = ty; i < 32; i += 8) {
        const float v = tile[tx][i];
        const size_t o = ((size_t)b * Tv + t0 + i) * Cv + c0 + tx;
        const __nv_bfloat16 h = __float2bfloat16(v);
        hi[o] = h;
        lo[o] = __float2bfloat16(v - __bfloat162float(h));
    }
}

// ---------------------------------------------------------------------------
// mask -> bitmask: g_BM[(b*T + t)*32 + w] bit i = (mask[b][t][w*32+i] != 0)
// grid (T/8, B), block 256 (8 warps; warp = one t row)
// ---------------------------------------------------------------------------
__global__ __launch_bounds__(256) void maskbits_kernel(const float* __restrict__ mask)
{
    const int b = blockIdx.y;
    const int t = blockIdx.x * 8 + (threadIdx.x >> 5);
    const int lane = threadIdx.x & 31;
    const float* row = mask + ((size_t)b * Tv + t) * Tv;
    uint32_t* dst = g_BM + ((size_t)b * Tv + t) * 32;
#pragma unroll 4
    for (int wd = 0; wd < 32; wd++) {
        const float v = row[wd * 32 + lane];
        const uint32_t word = __ballot_sync(0xffffffffu, v != 0.f);
        if (lane == 0) dst[wd] = word;
    }
}

// ---------------------------------------------------------------------------
// HMMA split-bf16 GEMM with register-prefetch pipeline.
// MODE 0: D[t][o] = act[t][:] . W[o][:]^T; out split bf16 [b][t][C] (Q/K)
// MODE 1: D[o][t] = W[o][:] . act[t][:]^T; out split bf16 [b][C][t] (V)
// MODE 2: D[o][t] ... out fp32 [b][C][t] (final projection)
// grid: MODE0 (C/128, T/128, B); MODE1/2 (T/128, C/128, B). block 256.
// D = Ah*Bh + Ah*Bl + Al*Bh, fp32 accumulators. value = (acc + bias[o]) * scale.
// ---------------------------------------------------------------------------
#define KCH 32
#define SSTR 40

template<int MODE>
__global__ __launch_bounds__(256) void hmma_gemm(
    const __nv_bfloat16* __restrict__ Wh_, const __nv_bfloat16* __restrict__ Wl_,
    const __nv_bfloat16* __restrict__ Acth, const __nv_bfloat16* __restrict__ Actl,
    const float* __restrict__ bias, float scale,
    float* __restrict__ outf,
    __nv_bfloat16* __restrict__ outhi, __nv_bfloat16* __restrict__ outlo)
{
    __shared__ __nv_bfloat16 sAh[128 * SSTR];
    __shared__ __nv_bfloat16 sAl[128 * SSTR];
    __shared__ __nv_bfloat16 sBh[128 * SSTR];
    __shared__ __nv_bfloat16 sBl[128 * SSTR];

    const int nblk = blockIdx.x * 128, mblk = blockIdx.y * 128, b = blockIdx.z;
    const int tid = threadIdx.x, wid = tid >> 5, lid = tid & 31;
    const int wm = wid >> 2, wn = wid & 3;
    const int m0 = wm * 64, n0 = wn * 32;
    const int g = lid >> 2, tg = lid & 3;

    const __nv_bfloat16 *pAh, *pAl, *pBh, *pBl;
    if (MODE == 0) {
        pAh = Acth + ((size_t)b * Tv + mblk) * Cv;
        pAl = Actl + ((size_t)b * Tv + mblk) * Cv;
        pBh = Wh_ + (size_t)nblk * Cv;
        pBl = Wl_ + (size_t)nblk * Cv;
    } else {
        pAh = Wh_ + (size_t)mblk * Cv;
        pAl = Wl_ + (size_t)mblk * Cv;
        pBh = Acth + ((size_t)b * Tv + nblk) * Cv;
        pBl = Actl + ((size_t)b * Tv + nblk) * Cv;
    }

    float acc[4][4][4];
#pragma unroll
    for (int mi = 0; mi < 4; mi++)
#pragma unroll
        for (int nj = 0; nj < 4; nj++)
#pragma unroll
            for (int r = 0; r < 4; r++) acc[mi][nj][r] = 0.f;

    uint4 ra_h[2], ra_l[2], rb_h[2], rb_l[2];
#pragma unroll
    for (int u = 0; u < 2; u++) {
        const int idx = tid + u * 256;
        const int r = idx >> 2, c8 = (idx & 3) * 8;
        ra_h[u] = *reinterpret_cast<const uint4*>(&pAh[(size_t)r * Cv + c8]);
        ra_l[u] = *reinterpret_cast<const uint4*>(&pAl[(size_t)r * Cv + c8]);
        rb_h[u] = *reinterpret_cast<const uint4*>(&pBh[(size_t)r * Cv + c8]);
        rb_l[u] = *reinterpret_cast<const uint4*>(&pBl[(size_t)r * Cv + c8]);
    }

    for (int kc0 = 0; kc0 < Cv; kc0 += KCH) {
        __syncthreads();
#pragma unroll
        for (int u = 0; u < 2; u++) {
            const int idx = tid + u * 256;
            const int r = idx >> 2, c8 = (idx & 3) * 8;
            *reinterpret_cast<uint4*>(&sAh[r * SSTR + c8]) = ra_h[u];
            *reinterpret_cast<uint4*>(&sAl[r * SSTR + c8]) = ra_l[u];
            *reinterpret_cast<uint4*>(&sBh[r * SSTR + c8]) = rb_h[u];
            *reinterpret_cast<uint4*>(&sBl[r * SSTR + c8]) = rb_l[u];
        }
        __syncthreads();
        if (kc0 + KCH < Cv) {
            const int kn = kc0 + KCH;
#pragma unroll
            for (int u = 0; u < 2; u++) {
                const int idx = tid + u * 256;
                const int r = idx >> 2, c8 = (idx & 3) * 8;
                ra_h[u] = *reinterpret_cast<const uint4*>(&pAh[(size_t)r * Cv + kn + c8]);
                ra_l[u] = *reinterpret_cast<const uint4*>(&pAl[(size_t)r * Cv + kn + c8]);
                rb_h[u] = *reinterpret_cast<const uint4*>(&pBh[(size_t)r * Cv + kn + c8]);
                rb_l[u] = *reinterpret_cast<const uint4*>(&pBl[(size_t)r * Cv + kn + c8]);
            }
        }

#pragma unroll
        for (int ks = 0; ks < KCH; ks += 16) {
            const int kk = ks + tg * 2;
            uint32_t ah[4][4], al[4][4], bh[4][2], bl[4][2];
#pragma unroll
            for (int mi = 0; mi < 4; mi++) {
                const int row = m0 + mi * 16 + g;
                ah[mi][0] = ldb32(&sAh[row * SSTR + kk]);
                ah[mi][1] = ldb32(&sAh[(row + 8) * SSTR + kk]);
                ah[mi][2] = ldb32(&sAh[row * SSTR + kk + 8]);
                ah[mi][3] = ldb32(&sAh[(row + 8) * SSTR + kk + 8]);
                al[mi][0] = ldb32(&sAl[row * SSTR + kk]);
                al[mi][1] = ldb32(&sAl[(row + 8) * SSTR + kk]);
                al[mi][2] = ldb32(&sAl[row * SSTR + kk + 8]);
                al[mi][3] = ldb32(&sAl[(row + 8) * SSTR + kk + 8]);
            }
#pragma unroll
            for (int nj = 0; nj < 4; nj++) {
                const int col = n0 + nj * 8 + g;
                bh[nj][0] = ldb32(&sBh[col * SSTR + kk]);
                bh[nj][1] = ldb32(&sBh[col * SSTR + kk + 8]);
                bl[nj][0] = ldb32(&sBl[col * SSTR + kk]);
                bl[nj][1] = ldb32(&sBl[col * SSTR + kk + 8]);
            }
#pragma unroll
            for (int mi = 0; mi < 4; mi++)
#pragma unroll
                for (int nj = 0; nj < 4; nj++) {
                    MMA16816(acc[mi][nj], ah[mi], bh[nj]);
                    MMA16816(acc[mi][nj], ah[mi], bl[nj]);
                    MMA16816(acc[mi][nj], al[mi], bh[nj]);
                }
        }
    }

    // ---- epilogues ----
    if (MODE == 0) {
        // rows m = t, cols n = o; pairs along o -> word at [b][t][o]
#pragma unroll
        for (int mi = 0; mi < 4; mi++) {
            const int t0r = mblk + m0 + mi * 16 + g;
#pragma unroll
            for (int nj = 0; nj < 4; nj++) {
                const int o = nblk + n0 + nj * 8 + tg * 2;
                const float b0 = bias[o], b1 = bias[o + 1];
                uint32_t hw, lw;
                pack_pair((acc[mi][nj][0] + b0) * scale, (acc[mi][nj][1] + b1) * scale, hw, lw);
                const size_t a0 = ((size_t)b * Tv + t0r) * Cv + o;
                *reinterpret_cast<uint32_t*>(&outhi[a0]) = hw;
                *reinterpret_cast<uint32_t*>(&outlo[a0]) = lw;
                pack_pair((acc[mi][nj][2] + b0) * scale, (acc[mi][nj][3] + b1) * scale, hw, lw);
                const size_t a1 = ((size_t)b * Tv + t0r + 8) * Cv + o;
                *reinterpret_cast<uint32_t*>(&outhi[a1]) = hw;
                *reinterpret_cast<uint32_t*>(&outlo[a1]) = lw;
            }
        }
    } else if (MODE == 1) {
        // rows m = o, cols n = t; pairs along t -> word at [b][o][t]
#pragma unroll
        for (int mi = 0; mi < 4; mi++) {
            const int o = mblk + m0 + mi * 16 + g;
            const float b0 = bias[o], b1 = bias[o + 8];
#pragma unroll
            for (int nj = 0; nj < 4; nj++) {
                const int t = nblk + n0 + nj * 8 + tg * 2;
                uint32_t hw, lw;
                pack_pair((acc[mi][nj][0] + b0) * scale, (acc[mi][nj][1] + b0) * scale, hw, lw);
                const size_t a0 = ((size_t)b * Cv + o) * Tv + t;
                *reinterpret_cast<uint32_t*>(&outhi[a0]) = hw;
                *reinterpret_cast<uint32_t*>(&outlo[a0]) = lw;
                pack_pair((acc[mi][nj][2] + b1) * scale, (acc[mi][nj][3] + b1) * scale, hw, lw);
                const size_t a1 = ((size_t)b * Cv + o + 8) * Tv + t;
                *reinterpret_cast<uint32_t*>(&outhi[a1]) = hw;
                *reinterpret_cast<uint32_t*>(&outlo[a1]) = lw;
            }
        }
    } else {
#pragma unroll
        for (int mi = 0; mi < 4; mi++) {
            const int o = mblk + m0 + mi * 16 + g;
            const float b0 = bias[o], b1 = bias[o + 8];
#pragma unroll
            for (int nj = 0; nj < 4; nj++) {
                const int t = nblk + n0 + nj * 8 + tg * 2;
                float2 v0, v1;
                v0.x = (acc[mi][nj][0] + b0) * scale;
                v0.y = (acc[mi][nj][1] + b0) * scale;
                v1.x = (acc[mi][nj][2] + b1) * scale;
                v1.y = (acc[mi][nj][3] + b1) * scale;
                *reinterpret_cast<float2*>(&outf[((size_t)b * Cv + o) * Tv + t]) = v0;
                *reinterpret_cast<float2*>(&outf[((size_t)b * Cv + o + 8) * Tv + t]) = v1;
            }
        }
    }
}

// ---------------------------------------------------------------------------
// HMMA banded flash attention, split-bf16 inputs pre-staged in global memory.
// grid (T/128, H, B), block 256 (8 warps x 16 rows). Q pre-scaled.
// Output written split-bf16 to g_Xhi/g_Xlo [b][t][C].
// 2 CTAs/SM (smem 92.7KB <= 114KB; no register prefetch to stay <= 128 regs).
// ---------------------------------------------------------------------------
#define QSTR 72

#define OFF_QH 0
#define OFF_QL (128 * QSTR)
#define OFF_KH (2 * 128 * QSTR)
#define OFF_KL (2 * 128 * QSTR + 64 * QSTR)
#define OFF_VH (2 * 128 * QSTR + 2 * 64 * QSTR)
#define OFF_VL (2 * 128 * QSTR + 3 * 64 * QSTR)
#define BF16_ELEMS (2 * 128 * QSTR + 4 * 64 * QSTR)
#define F_RK   0
#define F_BIAS (128 * 12)
#define F_EV   (128 * 12 + 516)
#define F_EK   (128 * 12 + 516 + 576)
#define F_PD   (128 * 12 + 516 + 2 * 576)
#define F_TOTAL (2 * 128 * 12 + 516 + 2 * 576)
#define ATTN_SMEM_BYTES (BF16_ELEMS * 2 + F_TOTAL * 4)

__global__ __launch_bounds__(256, 2) void attn_hmma(
    const float* __restrict__ ek, const float* __restrict__ ev)
{
    extern __shared__ __align__(16) char smem_raw[];
    __nv_bfloat16* sB16 = reinterpret_cast<__nv_bfloat16*>(smem_raw);
    float* sF = reinterpret_cast<float*>(smem_raw + BF16_ELEMS * 2);
    __nv_bfloat16* sQh = sB16 + OFF_QH;
    __nv_bfloat16* sQl = sB16 + OFF_QL;
    __nv_bfloat16* sKh = sB16 + OFF_KH;
    __nv_bfloat16* sKl = sB16 + OFF_KL;
    __nv_bfloat16* sVh = sB16 + OFF_VH;
    __nv_bfloat16* sVl = sB16 + OFF_VL;
    float* sRK   = sF + F_RK;
    float* sBias = sF + F_BIAS;
    float* sEV   = sF + F_EV;
    float* sEK   = sF + F_EK;
    float* sPd   = sF + F_PD;

    const int t0 = blockIdx.x * 128;
    const int h  = blockIdx.y;
    const int b  = blockIdx.z;
    const int tid = threadIdx.x, wid = tid >> 5, lid = tid & 31;
    const int g = lid >> 2, tg = lid & 3;
    const int wloc = wid * 16;

    // base pointers (row index = absolute t / s; no negative offsets)
    const __nv_bfloat16* Kh_b = g_Khi + ((size_t)b * Tv) * Cv + h * 64;
    const __nv_bfloat16* Kl_b = g_Klo + ((size_t)b * Tv) * Cv + h * 64;
    const __nv_bfloat16* Vh_b = g_Vhi + ((size_t)b * Cv + h * 64) * Tv;
    const __nv_bfloat16* Vl_b = g_Vlo + ((size_t)b * Cv + h * 64) * Tv;
    const size_t qrow0 = ((size_t)b * Tv + t0) * Cv + h * 64;

    // Load Q: 128 rows x 64 kc = 1024 uint4 per array
    for (int i = tid; i < 1024; i += 256) {
        const int t = i >> 3, seg = (i & 7) * 8;
        *reinterpret_cast<uint4*>(&sQh[t * QSTR + seg]) =
            *reinterpret_cast<const uint4*>(&g_Qhi[qrow0 + (size_t)t * Cv + seg]);
        *reinterpret_cast<uint4*>(&sQl[t * QSTR + seg]) =
            *reinterpret_cast<const uint4*>(&g_Qlo[qrow0 + (size_t)t * Cv + seg]);
    }
    for (int i = tid; i < 513; i += 256)
        sBias[i] = -log1pf(fabsf((float)(i - 256)));
    for (int i = tid; i < 576; i += 256) { sEK[i] = ek[i]; sEV[i] = ev[i]; }
    __syncthreads();

    // sRK[t][d] = sum_kc q[t][kc] * ek[d][kc]
    for (int i = tid; i < 1152; i += 256) {
        const int tl = i & 127, dd = i >> 7;
        float s = 0.f;
#pragma unroll 16
        for (int kc = 0; kc < 64; kc++) {
            const float q = __bfloat162float(sQh[tl * QSTR + kc]) +
                            __bfloat162float(sQl[tl * QSTR + kc]);
            s += q * sEK[dd * 64 + kc];
        }
        sRK[tl * 12 + dd] = s;
    }

    float m0 = -1e30f, m1 = -1e30f, l0 = 0.f, l1 = 0.f;
    float O[8][4];
#pragma unroll
    for (int nt = 0; nt < 8; nt++)
#pragma unroll
        for (int r = 0; r < 4; r++) O[nt][r] = 0.f;

    const int s_lo = max(0, t0 - 256);
    const int s_hi = min(Tv, t0 + 128 + 256);

    for (int s0 = s_lo; s0 < s_hi; s0 += 64) {
        const bool window = (s0 >= t0 - 64) && (s0 <= t0 + 128);
        __syncthreads();
        if (window) {
            for (int i = tid; i < 1536; i += 256) sPd[i] = 0.f;
        }
        // K/V chunk fill: 64 rows x 64 cols = 512 uint4 per array, 2 per thread
#pragma unroll
        for (int u = 0; u < 2; u++) {
            const int idx = tid + u * 256;
            const int fr = idx >> 3, fseg = (idx & 7) * 8;
            *reinterpret_cast<uint4*>(&sKh[fr * QSTR + fseg]) =
                *reinterpret_cast<const uint4*>(&Kh_b[(size_t)(s0 + fr) * Cv + fseg]);
            *reinterpret_cast<uint4*>(&sKl[fr * QSTR + fseg]) =
                *reinterpret_cast<const uint4*>(&Kl_b[(size_t)(s0 + fr) * Cv + fseg]);
            *reinterpret_cast<uint4*>(&sVh[fr * QSTR + fseg]) =
                *reinterpret_cast<const uint4*>(&Vh_b[(size_t)fr * Tv + s0 + fseg]);
            *reinterpret_cast<uint4*>(&sVl[fr * QSTR + fseg]) =
                *reinterpret_cast<const uint4*>(&Vl_b[(size_t)fr * Tv + s0 + fseg]);
        }
        __syncthreads();

        // mask bitmask words for this thread's two rows
        const int w0 = s0 >> 5;
        const int row0 = t0 + wloc + g;
        const uint32_t bA0 = g_BM[((size_t)b * Tv + row0) * 32 + w0];
        const uint32_t bA1 = g_BM[((size_t)b * Tv + row0) * 32 + w0 + 1];
        const uint32_t bB0 = g_BM[((size_t)b * Tv + row0 + 8) * 32 + w0];
        const uint32_t bB1 = g_BM[((size_t)b * Tv + row0 + 8) * 32 + w0 + 1];

        // ---- S = Q K^T ----
        float S[8][4];
#pragma unroll
        for (int nt = 0; nt < 8; nt++)
#pragma unroll
            for (int r = 0; r < 4; r++) S[nt][r] = 0.f;

#pragma unroll
        for (int ks = 0; ks < 4; ks++) {
            const int qr = (wloc + g) * QSTR + ks * 16 + tg * 2;
            uint32_t aqh[4], aql[4];
            aqh[0] = ldb32(&sQh[qr]);
            aqh[1] = ldb32(&sQh[qr + 8 * QSTR]);
            aqh[2] = ldb32(&sQh[qr + 8]);
            aqh[3] = ldb32(&sQh[qr + 8 * QSTR + 8]);
            aql[0] = ldb32(&sQl[qr]);
            aql[1] = ldb32(&sQl[qr + 8 * QSTR]);
            aql[2] = ldb32(&sQl[qr + 8]);
            aql[3] = ldb32(&sQl[qr + 8 * QSTR + 8]);
#pragma unroll
            for (int nt = 0; nt < 8; nt++) {
                const int kr = (nt * 8 + g) * QSTR + ks * 16 + tg * 2;
                uint32_t bh[2], bl[2];
                bh[0] = ldb32(&sKh[kr]);
                bh[1] = ldb32(&sKh[kr + 8]);
                bl[0] = ldb32(&sKl[kr]);
                bl[1] = ldb32(&sKl[kr + 8]);
                MMA16816(S[nt], aqh, bh);
                MMA16816(S[nt], aqh, bl);
                MMA16816(S[nt], aql, bh);
            }
        }

        // ---- biases + band + mask ----
#pragma unroll
        for (int nt = 0; nt < 8; nt++) {
#pragma unroll
            for (int r = 0; r < 4; r++) {
                const int tlr = wloc + g + ((r >> 1) << 3);
                const int t = t0 + tlr;
                const int si = nt * 8 + tg * 2 + (r & 1);
                const int s = s0 + si;
                const int d = s - t;
                float v = S[nt][r];
                if (d >= -256 && d <= 256) {
                    v += sBias[d + 256];
                    if (d >= -4 && d <= 4) v += sRK[tlr * 12 + d + 4];
                    const uint32_t wv = (r >> 1) ? ((si >= 32) ? bB1 : bB0)
                                                 : ((si >= 32) ? bA1 : bA0);
                    if (!((wv >> (si & 31)) & 1u)) v = -1e4f;
                } else {
                    v = -2e30f;
                }
                S[nt][r] = v;
            }
        }

        // ---- online softmax ----
        float rm0 = -2e30f, rm1 = -2e30f;
#pragma unroll
        for (int nt = 0; nt < 8; nt++) {
            rm0 = fmaxf(rm0, fmaxf(S[nt][0], S[nt][1]));
            rm1 = fmaxf(rm1, fmaxf(S[nt][2], S[nt][3]));
        }
        rm0 = fmaxf(rm0, __shfl_xor_sync(0xffffffffu, rm0, 1));
        rm0 = fmaxf(rm0, __shfl_xor_sync(0xffffffffu, rm0, 2));
        rm1 = fmaxf(rm1, __shfl_xor_sync(0xffffffffu, rm1, 1));
        rm1 = fmaxf(rm1, __shfl_xor_sync(0xffffffffu, rm1, 2));
        const float mn0 = fmaxf(m0, rm0), mn1 = fmaxf(m1, rm1);
        const float sc0 = __expf(m0 - mn0), sc1 = __expf(m1 - mn1);
        float rs0 = 0.f, rs1 = 0.f;
#pragma unroll
        for (int nt = 0; nt < 8; nt++) {
            S[nt][0] = __expf(S[nt][0] - mn0); rs0 += S[nt][0];
            S[nt][1] = __expf(S[nt][1] - mn0); rs0 += S[nt][1];
            S[nt][2] = __expf(S[nt][2] - mn1); rs1 += S[nt][2];
            S[nt][3] = __expf(S[nt][3] - mn1); rs1 += S[nt][3];
        }
        rs0 += __shfl_xor_sync(0xffffffffu, rs0, 1);
        rs0 += __shfl_xor_sync(0xffffffffu, rs0, 2);
        rs1 += __shfl_xor_sync(0xffffffffu, rs1, 1);
        rs1 += __shfl_xor_sync(0xffffffffu, rs1, 2);
        l0 = l0 * sc0 + rs0; l1 = l1 * sc1 + rs1;
        m0 = mn0; m1 = mn1;
#pragma unroll
        for (int nt = 0; nt < 8; nt++) {
            O[nt][0] *= sc0; O[nt][1] *= sc0;
            O[nt][2] *= sc1; O[nt][3] *= sc1;
        }

        // stash diagonal p's for rel-value stencil
        if (window) {
#pragma unroll
            for (int nt = 0; nt < 8; nt++) {
#pragma unroll
                for (int r = 0; r < 4; r++) {
                    const int tlr = wloc + g + ((r >> 1) << 3);
                    const int d = (s0 + nt * 8 + tg * 2 + (r & 1)) - (t0 + tlr);
                    if (d >= -4 && d <= 4) sPd[tlr * 12 + d + 4] = S[nt][r];
                }
            }
        }

        // ---- O += P V ----
#pragma unroll
        for (int ks = 0; ks < 4; ks++) {
            uint32_t aph[4], apl[4];
            pack_pair(S[2 * ks][0],     S[2 * ks][1],     aph[0], apl[0]);
            pack_pair(S[2 * ks][2],     S[2 * ks][3],     aph[1], apl[1]);
            pack_pair(S[2 * ks + 1][0], S[2 * ks + 1][1], aph[2], apl[2]);
            pack_pair(S[2 * ks + 1][2], S[2 * ks + 1][3], aph[3], apl[3]);
#pragma unroll
            for (int nt = 0; nt < 8; nt++) {
                const int vr = (nt * 8 + g) * QSTR + ks * 16 + tg * 2;
                uint32_t bh[2], bl[2];
                bh[0] = ldb32(&sVh[vr]);
                bh[1] = ldb32(&sVh[vr + 8]);
                bl[0] = ldb32(&sVl[vr]);
                bl[1] = ldb32(&sVl[vr + 8]);
                MMA16816(O[nt], aph, bh);
                MMA16816(O[nt], aph, bl);
                MMA16816(O[nt], apl, bh);
            }
        }

        // ---- rel-value 9-tap stencil ----
        if (window) {
            __syncthreads();
#pragma unroll
            for (int rh = 0; rh < 2; rh++) {
                const int tlr = wloc + g + rh * 8;
#pragma unroll
                for (int dd = 0; dd < 9; dd++) {
                    const float p = sPd[tlr * 12 + dd];
                    if (p != 0.f) {
#pragma unroll
                        for (int nt = 0; nt < 8; nt++) {
                            O[nt][2 * rh]     += p * sEV[dd * 64 + nt * 8 + tg * 2];
                            O[nt][2 * rh + 1] += p * sEV[dd * 64 + nt * 8 + tg * 2 + 1];
                        }
                    }
                }
            }
        }
    }

    // ---- finalize: normalize + direct split-bf16 store to g_X [b][t][C] ----
    const float inv0 = 1.f / l0, inv1 = 1.f / l1;
    const size_t out0 = ((size_t)b * Tv + t0 + wloc + g) * Cv + h * 64;
    const size_t out1 = out0 + 8 * Cv;
#pragma unroll
    for (int nt = 0; nt < 8; nt++) {
        const int kc = nt * 8 + tg * 2;
        uint32_t hw, lw;
        pack_pair(O[nt][0] * inv0, O[nt][1] * inv0, hw, lw);
        *reinterpret_cast<uint32_t*>(&g_Xhi[out0 + kc]) = hw;
        *reinterpret_cast<uint32_t*>(&g_Xlo[out0 + kc]) = lw;
        pack_pair(O[nt][2] * inv1, O[nt][3] * inv1, hw, lw);
        *reinterpret_cast<uint32_t*>(&g_Xhi[out1 + kc]) = hw;
        *reinterpret_cast<uint32_t*>(&g_Xlo[out1 + kc]) = lw;
    }
}

// ---------------------------------------------------------------------------

extern "C" void kernel_launch(void* const* d_in, const int* in_sizes, int n_in,
                              void* d_out, int out_size)
{
    const float* x    = (const float*)d_in[0];
    const float* c    = (const float*)d_in[1];
    const float* mask = (const float*)d_in[2];
    const float* Wq   = (const float*)d_in[3];
    const float* bq   = (const float*)d_in[4];
    const float* Wk   = (const float*)d_in[5];
    const float* bk   = (const float*)d_in[6];
    const float* Wv   = (const float*)d_in[7];
    const float* bv   = (const float*)d_in[8];
    const float* Wo   = (const float*)d_in[9];
    const float* bo   = (const float*)d_in[10];
    const float* ek   = (const float*)d_in[11];
    const float* ev   = (const float*)d_in[12];
    float* out = (float*)d_out;

    __nv_bfloat16 *whi, *wlo, *xhi, *xlo, *chi, *clo, *qhi, *qlo, *khi, *klo, *vhi, *vlo;
    cudaGetSymbolAddress((void**)&whi, g_Whi);
    cudaGetSymbolAddress((void**)&wlo, g_Wlo);
    cudaGetSymbolAddress((void**)&xhi, g_Xhi);
    cudaGetSymbolAddress((void**)&xlo, g_Xlo);
    cudaGetSymbolAddress((void**)&chi, g_Chi);
    cudaGetSymbolAddress((void**)&clo, g_Clo);
    cudaGetSymbolAddress((void**)&qhi, g_Qhi);
    cudaGetSymbolAddress((void**)&qlo, g_Qlo);
    cudaGetSymbolAddress((void**)&khi, g_Khi);
    cudaGetSymbolAddress((void**)&klo, g_Klo);
    cudaGetSymbolAddress((void**)&vhi, g_Vhi);
    cudaGetSymbolAddress((void**)&vlo, g_Vlo);

    cudaFuncSetAttribute(attn_hmma, cudaFuncAttributeMaxDynamicSharedMemorySize,
                         ATTN_SMEM_BYTES);

    const int WSZ = Cv * Cv;

    // pre-passes
    dim3 wg(WSZ / 256, 4);
    convw4_kernel<<<wg, 256>>>(Wq, Wk, Wv, Wo);
    dim3 tg(Tv / 32, Cv / 32, Bv), tb(32, 8);
    tconv_kernel<<<tg, tb>>>(x, xhi, xlo);
    tconv_kernel<<<tg, tb>>>(c, chi, clo);
    maskbits_kernel<<<dim3(Tv / 8, Bv), 256>>>(mask);

    // projections: Q/K transposed split outputs, V split [C][t]
    hmma_gemm<0><<<dim3(Cv / 128, Tv / 128, Bv), 256>>>(
        whi + 0 * WSZ, wlo + 0 * WSZ, xhi, xlo, bq, 0.125f, nullptr, qhi, qlo);
    hmma_gemm<0><<<dim3(Cv / 128, Tv / 128, Bv), 256>>>(
        whi + 1 * WSZ, wlo + 1 * WSZ, chi, clo, bk, 1.0f, nullptr, khi, klo);
    hmma_gemm<1><<<dim3(Tv / 128, Cv / 128, Bv), 256>>>(
        whi + 2 * WSZ, wlo + 2 * WSZ, chi, clo, bv, 1.0f, nullptr, vhi, vlo);

    // attention (writes split output into g_Xhi/g_Xlo)
    attn_hmma<<<dim3(Tv / 128, Hh, Bv), 256, ATTN_SMEM_BYTES>>>(ek, ev);

    // final projection (fp32 output)
    hmma_gemm<2><<<dim3(Tv / 128, Cv / 128, Bv), 256>>>(
        whi + 3 * WSZ, wlo + 3 * WSZ, xhi, xlo, bo, 1.0f, out, nullptr, nullptr);
}

// round 10
// speedup vs baseline: 2.4335x; 1.1014x over previous
#include <cuda_runtime.h>
#include <cuda_bf16.h>
#include <math.h>
#include <stdint.h>

#define Bv 8
#define Cv 512
#define Tv 1024
#define Hh 8
#define KCv 64

// ---------------------------------------------------------------------------
// Scratch (allocation-free rule: __device__ globals)
// ---------------------------------------------------------------------------
__device__ __nv_bfloat16 g_Whi[4 * Cv * Cv];
__device__ __nv_bfloat16 g_Wlo[4 * Cv * Cv];
__device__ __nv_bfloat16 g_Xhi[Bv * Tv * Cv];   // x^T split; later attention output
__device__ __nv_bfloat16 g_Xlo[Bv * Tv * Cv];
__device__ __nv_bfloat16 g_Chi[Bv * Tv * Cv];   // c^T split
__device__ __nv_bfloat16 g_Clo[Bv * Tv * Cv];
__device__ __nv_bfloat16 g_Qhi[Bv * Tv * Cv];   // Q split, [b][t][C], pre-scaled
__device__ __nv_bfloat16 g_Qlo[Bv * Tv * Cv];
__device__ __nv_bfloat16 g_Khi[Bv * Tv * Cv];   // K split, [b][t][C]
__device__ __nv_bfloat16 g_Klo[Bv * Tv * Cv];
__device__ __nv_bfloat16 g_Vhi[Bv * Cv * Tv];   // V split, [b][C][t]
__device__ __nv_bfloat16 g_Vlo[Bv * Cv * Tv];
__device__ uint32_t      g_BM[Bv * Tv * 32];    // mask bitmask, bit s of word w: s = w*32+bit

// ---------------------------------------------------------------------------
// mma.sync m16n8k16 bf16 -> f32 (classic HMMA; works on plain sm_103 target)
// ---------------------------------------------------------------------------
#define MMA16816(d, a, b) \
    asm volatile("mma.sync.aligned.m16n8k16.row.col.f32.bf16.bf16.f32 " \
        "{%0,%1,%2,%3}, {%4,%5,%6,%7}, {%8,%9}, {%0,%1,%2,%3};" \
        : "+f"((d)[0]), "+f"((d)[1]), "+f"((d)[2]), "+f"((d)[3]) \
        : "r"((a)[0]), "r"((a)[1]), "r"((a)[2]), "r"((a)[3]), \
          "r"((b)[0]), "r"((b)[1]))

#define CP_ASYNC16(saddr, gptr) \
    asm volatile("cp.async.cg.shared.global [%0], [%1], 16;" \
                 :: "r"(saddr), "l"(gptr) : "memory")
#define CP_COMMIT() asm volatile("cp.async.commit_group;" ::: "memory")
#define CP_WAIT1()  asm volatile("cp.async.wait_group 1;" ::: "memory")
#define CP_WAIT0()  asm volatile("cp.async.wait_group 0;" ::: "memory")

__device__ __forceinline__ uint32_t ldb32(const __nv_bfloat16* p) {
    return *reinterpret_cast<const uint32_t*>(p);
}
__device__ __forceinline__ uint32_t s2u(const void* p) {
    return (uint32_t)__cvta_generic_to_shared(p);
}
__device__ __forceinline__ void pack_pair(float x, float y, uint32_t& hi, uint32_t& lo) {
    const __nv_bfloat16 hx = __float2bfloat16(x), hy = __float2bfloat16(y);
    const __nv_bfloat16 lx = __float2bfloat16(x - __bfloat162float(hx));
    const __nv_bfloat16 ly = __float2bfloat16(y - __bfloat162float(hy));
    __nv_bfloat162 h2; h2.x = hx; h2.y = hy;
    __nv_bfloat162 l2; l2.x = lx; l2.y = ly;
    hi = *reinterpret_cast<const uint32_t*>(&h2);
    lo = *reinterpret_cast<const uint32_t*>(&l2);
}

// ---------------------------------------------------------------------------
// fp32 -> (hi, lo) bf16 split for 4 weight matrices in one launch
// ---------------------------------------------------------------------------
__global__ __launch_bounds__(256) void convw4_kernel(
    const float* __restrict__ w0, const float* __restrict__ w1,
    const float* __restrict__ w2, const float* __restrict__ w3)
{
    const int m = blockIdx.y;
    const float* w = (m == 0) ? w0 : (m == 1) ? w1 : (m == 2) ? w2 : w3;
    const int i = blockIdx.x * 256 + threadIdx.x;
    const float v = w[i];
    const __nv_bfloat16 h = __float2bfloat16(v);
    g_Whi[m * Cv * Cv + i] = h;
    g_Wlo[m * Cv * Cv + i] = __float2bfloat16(v - __bfloat162float(h));
}

// ---------------------------------------------------------------------------
// [b][c][t] fp32 -> [b][t][c] bf16 hi/lo (transpose + split)
// grid (T/32, C/32, B), block (32, 8)
// ---------------------------------------------------------------------------
__global__ __launch_bounds__(256) void tconv_kernel(
    const float* __restrict__ in, __nv_bfloat16* __restrict__ hi, __nv_bfloat16* __restrict__ lo)
{
    __shared__ float tile[32][33];
    const int b = blockIdx.z, c0 = blockIdx.y * 32, t0 = blockIdx.x * 32;
    const int tx = threadIdx.x, ty = threadIdx.y;
    const float* src = in + ((size_t)b * Cv + c0) * Tv + t0;
#pragma unroll
    for (int i = ty; i < 32; i += 8)
        tile[i][tx] = src[(size_t)i * Tv + tx];
    __syncthreads();
#pragma unroll
    for (int i = ty; i < 32; i += 8) {
        const float v = tile[tx][i];
        const size_t o = ((size_t)b * Tv + t0 + i) * Cv + c0 + tx;
        const __nv_bfloat16 h = __float2bfloat16(v);
        hi[o] = h;
        lo[o] = __float2bfloat16(v - __bfloat162float(h));
    }
}

// ---------------------------------------------------------------------------
// mask -> bitmask: g_BM[(b*T + t)*32 + w] bit i = (mask[b][t][w*32+i] != 0)
// grid (T/8, B), block 256 (8 warps; warp = one t row)
// ---------------------------------------------------------------------------
__global__ __launch_bounds__(256) void maskbits_kernel(const float* __restrict__ mask)
{
    const int b = blockIdx.y;
    const int t = blockIdx.x * 8 + (threadIdx.x >> 5);
    const int lane = threadIdx.x & 31;
    const float* row = mask + ((size_t)b * Tv + t) * Tv;
    uint32_t* dst = g_BM + ((size_t)b * Tv + t) * 32;
#pragma unroll 4
    for (int wd = 0; wd < 32; wd++) {
        const float v = row[wd * 32 + lane];
        const uint32_t word = __ballot_sync(0xffffffffu, v != 0.f);
        if (lane == 0) dst[wd] = word;
    }
}

// ---------------------------------------------------------------------------
// HMMA split-bf16 GEMM, cp.async double-buffered pipeline.
// MODE 0: D[t][o] = act[t][:] . W[o][:]^T; out split bf16 [b][t][C] (Q/K)
// MODE 1: D[o][t] = W[o][:] . act[t][:]^T; out split bf16 [b][C][t] (V)
// MODE 2: D[o][t] ... out fp32 [b][C][t] (final projection)
// grid: MODE0 (C/128, T/128, B); MODE1/2 (T/128, C/128, B). block 256.
// D = Ah*Bh + Ah*Bl + Al*Bh, fp32 accumulators. value = (acc + bias[o]) * scale.
// ---------------------------------------------------------------------------
#define KCH 32
#define SSTR 40
#define GARR (128 * SSTR)            // elems per array
#define GSTAGE (4 * GARR)            // elems per stage (Ah, Al, Bh, Bl)
#define GEMM_SMEM_BYTES (2 * GSTAGE * 2)

__device__ __forceinline__ void gemm_stage_cp(
    __nv_bfloat16* st, const __nv_bfloat16* pAh, const __nv_bfloat16* pAl,
    const __nv_bfloat16* pBh, const __nv_bfloat16* pBl, int kc0, int tid)
{
    __nv_bfloat16* sAh = st;
    __nv_bfloat16* sAl = st + GARR;
    __nv_bfloat16* sBh = st + 2 * GARR;
    __nv_bfloat16* sBl = st + 3 * GARR;
#pragma unroll
    for (int u = 0; u < 2; u++) {
        const int idx = tid + u * 256;
        const int r = idx >> 2, c8 = (idx & 3) * 8;
        const size_t go = (size_t)r * Cv + kc0 + c8;
        const uint32_t so = (uint32_t)(r * SSTR + c8);
        CP_ASYNC16(s2u(sAh + so), pAh + go);
        CP_ASYNC16(s2u(sAl + so), pAl + go);
        CP_ASYNC16(s2u(sBh + so), pBh + go);
        CP_ASYNC16(s2u(sBl + so), pBl + go);
    }
}

template<int MODE>
__global__ __launch_bounds__(256, 2) void hmma_gemm(
    const __nv_bfloat16* __restrict__ Wh_, const __nv_bfloat16* __restrict__ Wl_,
    const __nv_bfloat16* __restrict__ Acth, const __nv_bfloat16* __restrict__ Actl,
    const float* __restrict__ bias, float scale,
    float* __restrict__ outf,
    __nv_bfloat16* __restrict__ outhi, __nv_bfloat16* __restrict__ outlo)
{
    extern __shared__ __align__(16) __nv_bfloat16 gsm[];

    const int nblk = blockIdx.x * 128, mblk = blockIdx.y * 128, b = blockIdx.z;
    const int tid = threadIdx.x, wid = tid >> 5, lid = tid & 31;
    const int wm = wid >> 2, wn = wid & 3;
    const int m0 = wm * 64, n0 = wn * 32;
    const int g = lid >> 2, tg = lid & 3;

    const __nv_bfloat16 *pAh, *pAl, *pBh, *pBl;
    if (MODE == 0) {
        pAh = Acth + ((size_t)b * Tv + mblk) * Cv;
        pAl = Actl + ((size_t)b * Tv + mblk) * Cv;
        pBh = Wh_ + (size_t)nblk * Cv;
        pBl = Wl_ + (size_t)nblk * Cv;
    } else {
        pAh = Wh_ + (size_t)mblk * Cv;
        pAl = Wl_ + (size_t)mblk * Cv;
        pBh = Acth + ((size_t)b * Tv + nblk) * Cv;
        pBl = Actl + ((size_t)b * Tv + nblk) * Cv;
    }

    float acc[4][4][4];
#pragma unroll
    for (int mi = 0; mi < 4; mi++)
#pragma unroll
        for (int nj = 0; nj < 4; nj++)
#pragma unroll
            for (int r = 0; r < 4; r++) acc[mi][nj][r] = 0.f;

    // prologue: stage 0
    gemm_stage_cp(gsm, pAh, pAl, pBh, pBl, 0, tid);
    CP_COMMIT();

    for (int kc0 = 0, it = 0; kc0 < Cv; kc0 += KCH, it++) {
        if (kc0 + KCH < Cv) {
            gemm_stage_cp(gsm + ((it + 1) & 1) * GSTAGE, pAh, pAl, pBh, pBl,
                          kc0 + KCH, tid);
            CP_COMMIT();
            CP_WAIT1();
        } else {
            CP_WAIT0();
        }
        __syncthreads();

        const __nv_bfloat16* st = gsm + (it & 1) * GSTAGE;
        const __nv_bfloat16* sAh = st;
        const __nv_bfloat16* sAl = st + GARR;
        const __nv_bfloat16* sBh = st + 2 * GARR;
        const __nv_bfloat16* sBl = st + 3 * GARR;

#pragma unroll
        for (int ks = 0; ks < KCH; ks += 16) {
            const int kk = ks + tg * 2;
            uint32_t ah[4][4], al[4][4], bh[4][2], bl[4][2];
#pragma unroll
            for (int mi = 0; mi < 4; mi++) {
                const int row = m0 + mi * 16 + g;
                ah[mi][0] = ldb32(&sAh[row * SSTR + kk]);
                ah[mi][1] = ldb32(&sAh[(row + 8) * SSTR + kk]);
                ah[mi][2] = ldb32(&sAh[row * SSTR + kk + 8]);
                ah[mi][3] = ldb32(&sAh[(row + 8) * SSTR + kk + 8]);
                al[mi][0] = ldb32(&sAl[row * SSTR + kk]);
                al[mi][1] = ldb32(&sAl[(row + 8) * SSTR + kk]);
                al[mi][2] = ldb32(&sAl[row * SSTR + kk + 8]);
                al[mi][3] = ldb32(&sAl[(row + 8) * SSTR + kk + 8]);
            }
#pragma unroll
            for (int nj = 0; nj < 4; nj++) {
                const int col = n0 + nj * 8 + g;
                bh[nj][0] = ldb32(&sBh[col * SSTR + kk]);
                bh[nj][1] = ldb32(&sBh[col * SSTR + kk + 8]);
                bl[nj][0] = ldb32(&sBl[col * SSTR + kk]);
                bl[nj][1] = ldb32(&sBl[col * SSTR + kk + 8]);
            }
#pragma unroll
            for (int mi = 0; mi < 4; mi++)
#pragma unroll
                for (int nj = 0; nj < 4; nj++) {
                    MMA16816(acc[mi][nj], ah[mi], bh[nj]);
                    MMA16816(acc[mi][nj], ah[mi], bl[nj]);
                    MMA16816(acc[mi][nj], al[mi], bh[nj]);
                }
        }
        __syncthreads();  // all reads of this stage done before it is refilled
    }

    // ---- epilogues ----
    if (MODE == 0) {
        // rows m = t, cols n = o; pairs along o -> word at [b][t][o]
#pragma unroll
        for (int mi = 0; mi < 4; mi++) {
            const int t0r = mblk + m0 + mi * 16 + g;
#pragma unroll
            for (int nj = 0; nj < 4; nj++) {
                const int o = nblk + n0 + nj * 8 + tg * 2;
                const float b0 = bias[o], b1 = bias[o + 1];
                uint32_t hw, lw;
                pack_pair((acc[mi][nj][0] + b0) * scale, (acc[mi][nj][1] + b1) * scale, hw, lw);
                const size_t a0 = ((size_t)b * Tv + t0r) * Cv + o;
                *reinterpret_cast<uint32_t*>(&outhi[a0]) = hw;
                *reinterpret_cast<uint32_t*>(&outlo[a0]) = lw;
                pack_pair((acc[mi][nj][2] + b0) * scale, (acc[mi][nj][3] + b1) * scale, hw, lw);
                const size_t a1 = ((size_t)b * Tv + t0r + 8) * Cv + o;
                *reinterpret_cast<uint32_t*>(&outhi[a1]) = hw;
                *reinterpret_cast<uint32_t*>(&outlo[a1]) = lw;
            }
        }
    } else if (MODE == 1) {
        // rows m = o, cols n = t; pairs along t -> word at [b][o][t]
#pragma unroll
        for (int mi = 0; mi < 4; mi++) {
            const int o = mblk + m0 + mi * 16 + g;
            const float b0 = bias[o], b1 = bias[o + 8];
#pragma unroll
            for (int nj = 0; nj < 4; nj++) {
                const int t = nblk + n0 + nj * 8 + tg * 2;
                uint32_t hw, lw;
                pack_pair((acc[mi][nj][0] + b0) * scale, (acc[mi][nj][1] + b0) * scale, hw, lw);
                const size_t a0 = ((size_t)b * Cv + o) * Tv + t;
                *reinterpret_cast<uint32_t*>(&outhi[a0]) = hw;
                *reinterpret_cast<uint32_t*>(&outlo[a0]) = lw;
                pack_pair((acc[mi][nj][2] + b1) * scale, (acc[mi][nj][3] + b1) * scale, hw, lw);
                const size_t a1 = ((size_t)b * Cv + o + 8) * Tv + t;
                *reinterpret_cast<uint32_t*>(&outhi[a1]) = hw;
                *reinterpret_cast<uint32_t*>(&outlo[a1]) = lw;
            }
        }
    } else {
#pragma unroll
        for (int mi = 0; mi < 4; mi++) {
            const int o = mblk + m0 + mi * 16 + g;
            const float b0 = bias[o], b1 = bias[o + 8];
#pragma unroll
            for (int nj = 0; nj < 4; nj++) {
                const int t = nblk + n0 + nj * 8 + tg * 2;
                float2 v0, v1;
                v0.x = (acc[mi][nj][0] + b0) * scale;
                v0.y = (acc[mi][nj][1] + b0) * scale;
                v1.x = (acc[mi][nj][2] + b1) * scale;
                v1.y = (acc[mi][nj][3] + b1) * scale;
                *reinterpret_cast<float2*>(&outf[((size_t)b * Cv + o) * Tv + t]) = v0;
                *reinterpret_cast<float2*>(&outf[((size_t)b * Cv + o + 8) * Tv + t]) = v1;
            }
        }
    }
}

// ---------------------------------------------------------------------------
// HMMA banded flash attention, split-bf16 inputs pre-staged in global memory.
// grid (T/128, H, B), block 256 (8 warps x 16 rows). Q pre-scaled.
// Output written split-bf16 to g_Xhi/g_Xlo [b][t][C]. 2 CTAs/SM.
// Per-warp out-of-band chunk skip (exact: skipped chunks are softmax no-ops).
// ---------------------------------------------------------------------------
#define QSTR 72

#define OFF_QH 0
#define OFF_QL (128 * QSTR)
#define OFF_KH (2 * 128 * QSTR)
#define OFF_KL (2 * 128 * QSTR + 64 * QSTR)
#define OFF_VH (2 * 128 * QSTR + 2 * 64 * QSTR)
#define OFF_VL (2 * 128 * QSTR + 3 * 64 * QSTR)
#define BF16_ELEMS (2 * 128 * QSTR + 4 * 64 * QSTR)
#define F_RK   0
#define F_BIAS (128 * 12)
#define F_EV   (128 * 12 + 516)
#define F_EK   (128 * 12 + 516 + 576)
#define F_PD   (128 * 12 + 516 + 2 * 576)
#define F_TOTAL (2 * 128 * 12 + 516 + 2 * 576)
#define ATTN_SMEM_BYTES (BF16_ELEMS * 2 + F_TOTAL * 4)

__global__ __launch_bounds__(256, 2) void attn_hmma(
    const float* __restrict__ ek, const float* __restrict__ ev)
{
    extern __shared__ __align__(16) char smem_raw[];
    __nv_bfloat16* sB16 = reinterpret_cast<__nv_bfloat16*>(smem_raw);
    float* sF = reinterpret_cast<float*>(smem_raw + BF16_ELEMS * 2);
    __nv_bfloat16* sQh = sB16 + OFF_QH;
    __nv_bfloat16* sQl = sB16 + OFF_QL;
    __nv_bfloat16* sKh = sB16 + OFF_KH;
    __nv_bfloat16* sKl = sB16 + OFF_KL;
    __nv_bfloat16* sVh = sB16 + OFF_VH;
    __nv_bfloat16* sVl = sB16 + OFF_VL;
    float* sRK   = sF + F_RK;
    float* sBias = sF + F_BIAS;
    float* sEV   = sF + F_EV;
    float* sEK   = sF + F_EK;
    float* sPd   = sF + F_PD;

    const int t0 = blockIdx.x * 128;
    const int h  = blockIdx.y;
    const int b  = blockIdx.z;
    const int tid = threadIdx.x, wid = tid >> 5, lid = tid & 31;
    const int g = lid >> 2, tg = lid & 3;
    const int wloc = wid * 16;

    // base pointers (row index = absolute t / s; no negative offsets)
    const __nv_bfloat16* Kh_b = g_Khi + ((size_t)b * Tv) * Cv + h * 64;
    const __nv_bfloat16* Kl_b = g_Klo + ((size_t)b * Tv) * Cv + h * 64;
    const __nv_bfloat16* Vh_b = g_Vhi + ((size_t)b * Cv + h * 64) * Tv;
    const __nv_bfloat16* Vl_b = g_Vlo + ((size_t)b * Cv + h * 64) * Tv;
    const size_t qrow0 = ((size_t)b * Tv + t0) * Cv + h * 64;

    // Load Q: 128 rows x 64 kc = 1024 uint4 per array
    for (int i = tid; i < 1024; i += 256) {
        const int t = i >> 3, seg = (i & 7) * 8;
        *reinterpret_cast<uint4*>(&sQh[t * QSTR + seg]) =
            *reinterpret_cast<const uint4*>(&g_Qhi[qrow0 + (size_t)t * Cv + seg]);
        *reinterpret_cast<uint4*>(&sQl[t * QSTR + seg]) =
            *reinterpret_cast<const uint4*>(&g_Qlo[qrow0 + (size_t)t * Cv + seg]);
    }
    for (int i = tid; i < 513; i += 256)
        sBias[i] = -log1pf(fabsf((float)(i - 256)));
    for (int i = tid; i < 576; i += 256) { sEK[i] = ek[i]; sEV[i] = ev[i]; }
    __syncthreads();

    // sRK[t][d] = sum_kc q[t][kc] * ek[d][kc]
    for (int i = tid; i < 1152; i += 256) {
        const int tl = i & 127, dd = i >> 7;
        float s = 0.f;
#pragma unroll 16
        for (int kc = 0; kc < 64; kc++) {
            const float q = __bfloat162float(sQh[tl * QSTR + kc]) +
                            __bfloat162float(sQl[tl * QSTR + kc]);
            s += q * sEK[dd * 64 + kc];
        }
        sRK[tl * 12 + dd] = s;
    }

    float m0 = -1e30f, m1 = -1e30f, l0 = 0.f, l1 = 0.f;
    float O[8][4];
#pragma unroll
    for (int nt = 0; nt < 8; nt++)
#pragma unroll
        for (int r = 0; r < 4; r++) O[nt][r] = 0.f;

    const int s_lo = max(0, t0 - 256);
    const int s_hi = min(Tv, t0 + 128 + 256);

    for (int s0 = s_lo; s0 < s_hi; s0 += 64) {
        const bool window = (s0 >= t0 - 64) && (s0 <= t0 + 128);
        // per-warp band intersection: rows [t0+wloc, t0+wloc+15]
        const bool active = (s0 + 63 >= t0 + wloc - 256) && (s0 <= t0 + wloc + 15 + 256);
        __syncthreads();
        if (window) {
            for (int i = tid; i < 1536; i += 256) sPd[i] = 0.f;
        }
        // K/V chunk fill: 64 rows x 64 cols = 512 uint4 per array, 2 per thread
#pragma unroll
        for (int u = 0; u < 2; u++) {
            const int idx = tid + u * 256;
            const int fr = idx >> 3, fseg = (idx & 7) * 8;
            *reinterpret_cast<uint4*>(&sKh[fr * QSTR + fseg]) =
                *reinterpret_cast<const uint4*>(&Kh_b[(size_t)(s0 + fr) * Cv + fseg]);
            *reinterpret_cast<uint4*>(&sKl[fr * QSTR + fseg]) =
                *reinterpret_cast<const uint4*>(&Kl_b[(size_t)(s0 + fr) * Cv + fseg]);
            *reinterpret_cast<uint4*>(&sVh[fr * QSTR + fseg]) =
                *reinterpret_cast<const uint4*>(&Vh_b[(size_t)fr * Tv + s0 + fseg]);
            *reinterpret_cast<uint4*>(&sVl[fr * QSTR + fseg]) =
                *reinterpret_cast<const uint4*>(&Vl_b[(size_t)fr * Tv + s0 + fseg]);
        }
        __syncthreads();

        if (!active) continue;

        // mask bitmask words for this thread's two rows
        const int w0 = s0 >> 5;
        const int row0 = t0 + wloc + g;
        const uint32_t bA0 = g_BM[((size_t)b * Tv + row0) * 32 + w0];
        const uint32_t bA1 = g_BM[((size_t)b * Tv + row0) * 32 + w0 + 1];
        const uint32_t bB0 = g_BM[((size_t)b * Tv + row0 + 8) * 32 + w0];
        const uint32_t bB1 = g_BM[((size_t)b * Tv + row0 + 8) * 32 + w0 + 1];

        // ---- S = Q K^T ----
        float S[8][4];
#pragma unroll
        for (int nt = 0; nt < 8; nt++)
#pragma unroll
            for (int r = 0; r < 4; r++) S[nt][r] = 0.f;

#pragma unroll
        for (int ks = 0; ks < 4; ks++) {
            const int qr = (wloc + g) * QSTR + ks * 16 + tg * 2;
            uint32_t aqh[4], aql[4];
            aqh[0] = ldb32(&sQh[qr]);
            aqh[1] = ldb32(&sQh[qr + 8 * QSTR]);
            aqh[2] = ldb32(&sQh[qr + 8]);
            aqh[3] = ldb32(&sQh[qr + 8 * QSTR + 8]);
            aql[0] = ldb32(&sQl[qr]);
            aql[1] = ldb32(&sQl[qr + 8 * QSTR]);
            aql[2] = ldb32(&sQl[qr + 8]);
            aql[3] = ldb32(&sQl[qr + 8 * QSTR + 8]);
#pragma unroll
            for (int nt = 0; nt < 8; nt++) {
                const int kr = (nt * 8 + g) * QSTR + ks * 16 + tg * 2;
                uint32_t bh[2], bl[2];
                bh[0] = ldb32(&sKh[kr]);
                bh[1] = ldb32(&sKh[kr + 8]);
                bl[0] = ldb32(&sKl[kr]);
                bl[1] = ldb32(&sKl[kr + 8]);
                MMA16816(S[nt], aqh, bh);
                MMA16816(S[nt], aqh, bl);
                MMA16816(S[nt], aql, bh);
            }
        }

        // ---- biases + band + mask ----
#pragma unroll
        for (int nt = 0; nt < 8; nt++) {
#pragma unroll
            for (int r = 0; r < 4; r++) {
                const int tlr = wloc + g + ((r >> 1) << 3);
                const int t = t0 + tlr;
                const int si = nt * 8 + tg * 2 + (r & 1);
                const int s = s0 + si;
                const int d = s - t;
                float v = S[nt][r];
                if (d >= -256 && d <= 256) {
                    v += sBias[d + 256];
                    if (d >= -4 && d <= 4) v += sRK[tlr * 12 + d + 4];
                    const uint32_t wv = (r >> 1) ? ((si >= 32) ? bB1 : bB0)
                                                 : ((si >= 32) ? bA1 : bA0);
                    if (!((wv >> (si & 31)) & 1u)) v = -1e4f;
                } else {
                    v = -2e30f;
                }
                S[nt][r] = v;
            }
        }

        // ---- online softmax ----
        float rm0 = -2e30f, rm1 = -2e30f;
#pragma unroll
        for (int nt = 0; nt < 8; nt++) {
            rm0 = fmaxf(rm0, fmaxf(S[nt][0], S[nt][1]));
            rm1 = fmaxf(rm1, fmaxf(S[nt][2], S[nt][3]));
        }
        rm0 = fmaxf(rm0, __shfl_xor_sync(0xffffffffu, rm0, 1));
        rm0 = fmaxf(rm0, __shfl_xor_sync(0xffffffffu, rm0, 2));
        rm1 = fmaxf(rm1, __shfl_xor_sync(0xffffffffu, rm1, 1));
        rm1 = fmaxf(rm1, __shfl_xor_sync(0xffffffffu, rm1, 2));
        const float mn0 = fmaxf(m0, rm0), mn1 = fmaxf(m1, rm1);
        const float sc0 = __expf(m0 - mn0), sc1 = __expf(m1 - mn1);
        float rs0 = 0.f, rs1 = 0.f;
#pragma unroll
        for (int nt = 0; nt < 8; nt++) {
            S[nt][0] = __expf(S[nt][0] - mn0); rs0 += S[nt][0];
            S[nt][1] = __expf(S[nt][1] - mn0); rs0 += S[nt][1];
            S[nt][2] = __expf(S[nt][2] - mn1); rs1 += S[nt][2];
            S[nt][3] = __expf(S[nt][3] - mn1); rs1 += S[nt][3];
        }
        rs0 += __shfl_xor_sync(0xffffffffu, rs0, 1);
        rs0 += __shfl_xor_sync(0xffffffffu, rs0, 2);
        rs1 += __shfl_xor_sync(0xffffffffu, rs1, 1);
        rs1 += __shfl_xor_sync(0xffffffffu, rs1, 2);
        l0 = l0 * sc0 + rs0; l1 = l1 * sc1 + rs1;
        m0 = mn0; m1 = mn1;
#pragma unroll
        for (int nt = 0; nt < 8; nt++) {
            O[nt][0] *= sc0; O[nt][1] *= sc0;
            O[nt][2] *= sc1; O[nt][3] *= sc1;
        }

        // stash diagonal p's for rel-value stencil (sPd rows are warp-exclusive)
        if (window) {
#pragma unroll
            for (int nt = 0; nt < 8; nt++) {
#pragma unroll
                for (int r = 0; r < 4; r++) {
                    const int tlr = wloc + g + ((r >> 1) << 3);
                    const int d = (s0 + nt * 8 + tg * 2 + (r & 1)) - (t0 + tlr);
                    if (d >= -4 && d <= 4) sPd[tlr * 12 + d + 4] = S[nt][r];
                }
            }
        }

        // ---- O += P V ----
#pragma unroll
        for (int ks = 0; ks < 4; ks++) {
            uint32_t aph[4], apl[4];
            pack_pair(S[2 * ks][0],     S[2 * ks][1],     aph[0], apl[0]);
            pack_pair(S[2 * ks][2],     S[2 * ks][3],     aph[1], apl[1]);
            pack_pair(S[2 * ks + 1][0], S[2 * ks + 1][1], aph[2], apl[2]);
            pack_pair(S[2 * ks + 1][2], S[2 * ks + 1][3], aph[3], apl[3]);
#pragma unroll
            for (int nt = 0; nt < 8; nt++) {
                const int vr = (nt * 8 + g) * QSTR + ks * 16 + tg * 2;
                uint32_t bh[2], bl[2];
                bh[0] = ldb32(&sVh[vr]);
                bh[1] = ldb32(&sVh[vr + 8]);
                bl[0] = ldb32(&sVl[vr]);
                bl[1] = ldb32(&sVl[vr + 8]);
                MMA16816(O[nt], aph, bh);
                MMA16816(O[nt], aph, bl);
                MMA16816(O[nt], apl, bh);
            }
        }

        // ---- rel-value 9-tap stencil (same-warp rows; __syncwarp suffices) ----
        if (window) {
            __syncwarp();
#pragma unroll
            for (int rh = 0; rh < 2; rh++) {
                const int tlr = wloc + g + rh * 8;
#pragma unroll
                for (int dd = 0; dd < 9; dd++) {
                    const float p = sPd[tlr * 12 + dd];
                    if (p != 0.f) {
#pragma unroll
                        for (int nt = 0; nt < 8; nt++) {
                            O[nt][2 * rh]     += p * sEV[dd * 64 + nt * 8 + tg * 2];
                            O[nt][2 * rh + 1] += p * sEV[dd * 64 + nt * 8 + tg * 2 + 1];
                        }
                    }
                }
            }
        }
    }

    // ---- finalize: normalize + direct split-bf16 store to g_X [b][t][C] ----
    const float inv0 = 1.f / l0, inv1 = 1.f / l1;
    const size_t out0 = ((size_t)b * Tv + t0 + wloc + g) * Cv + h * 64;
    const size_t out1 = out0 + 8 * Cv;
#pragma unroll
    for (int nt = 0; nt < 8; nt++) {
        const int kc = nt * 8 + tg * 2;
        uint32_t hw, lw;
        pack_pair(O[nt][0] * inv0, O[nt][1] * inv0, hw, lw);
        *reinterpret_cast<uint32_t*>(&g_Xhi[out0 + kc]) = hw;
        *reinterpret_cast<uint32_t*>(&g_Xlo[out0 + kc]) = lw;
        pack_pair(O[nt][2] * inv1, O[nt][3] * inv1, hw, lw);
        *reinterpret_cast<uint32_t*>(&g_Xhi[out1 + kc]) = hw;
        *reinterpret_cast<uint32_t*>(&g_Xlo[out1 + kc]) = lw;
    }
}

// ---------------------------------------------------------------------------

extern "C" void kernel_launch(void* const* d_in, const int* in_sizes, int n_in,
                              void* d_out, int out_size)
{
    const float* x    = (const float*)d_in[0];
    const float* c    = (const float*)d_in[1];
    const float* mask = (const float*)d_in[2];
    const float* Wq   = (const float*)d_in[3];
    const float* bq   = (const float*)d_in[4];
    const float* Wk   = (const float*)d_in[5];
    const float* bk   = (const float*)d_in[6];
    const float* Wv   = (const float*)d_in[7];
    const float* bv   = (const float*)d_in[8];
    const float* Wo   = (const float*)d_in[9];
    const float* bo   = (const float*)d_in[10];
    const float* ek   = (const float*)d_in[11];
    const float* ev   = (const float*)d_in[12];
    float* out = (float*)d_out;

    __nv_bfloat16 *whi, *wlo, *xhi, *xlo, *chi, *clo, *qhi, *qlo, *khi, *klo, *vhi, *vlo;
    cudaGetSymbolAddress((void**)&whi, g_Whi);
    cudaGetSymbolAddress((void**)&wlo, g_Wlo);
    cudaGetSymbolAddress((void**)&xhi, g_Xhi);
    cudaGetSymbolAddress((void**)&xlo, g_Xlo);
    cudaGetSymbolAddress((void**)&chi, g_Chi);
    cudaGetSymbolAddress((void**)&clo, g_Clo);
    cudaGetSymbolAddress((void**)&qhi, g_Qhi);
    cudaGetSymbolAddress((void**)&qlo, g_Qlo);
    cudaGetSymbolAddress((void**)&khi, g_Khi);
    cudaGetSymbolAddress((void**)&klo, g_Klo);
    cudaGetSymbolAddress((void**)&vhi, g_Vhi);
    cudaGetSymbolAddress((void**)&vlo, g_Vlo);

    cudaFuncSetAttribute(attn_hmma, cudaFuncAttributeMaxDynamicSharedMemorySize,
                         ATTN_SMEM_BYTES);
    cudaFuncSetAttribute(hmma_gemm<0>, cudaFuncAttributeMaxDynamicSharedMemorySize,
                         GEMM_SMEM_BYTES);
    cudaFuncSetAttribute(hmma_gemm<1>, cudaFuncAttributeMaxDynamicSharedMemorySize,
                         GEMM_SMEM_BYTES);
    cudaFuncSetAttribute(hmma_gemm<2>, cudaFuncAttributeMaxDynamicSharedMemorySize,
                         GEMM_SMEM_BYTES);

    const int WSZ = Cv * Cv;

    // pre-passes
    dim3 wg(WSZ / 256, 4);
    convw4_kernel<<<wg, 256>>>(Wq, Wk, Wv, Wo);
    dim3 tg(Tv / 32, Cv / 32, Bv), tb(32, 8);
    tconv_kernel<<<tg, tb>>>(x, xhi, xlo);
    tconv_kernel<<<tg, tb>>>(c, chi, clo);
    maskbits_kernel<<<dim3(Tv / 8, Bv), 256>>>(mask);

    // projections: Q/K transposed split outputs, V split [C][t]
    hmma_gemm<0><<<dim3(Cv / 128, Tv / 128, Bv), 256, GEMM_SMEM_BYTES>>>(
        whi + 0 * WSZ, wlo + 0 * WSZ, xhi, xlo, bq, 0.125f, nullptr, qhi, qlo);
    hmma_gemm<0><<<dim3(Cv / 128, Tv / 128, Bv), 256, GEMM_SMEM_BYTES>>>(
        whi + 1 * WSZ, wlo + 1 * WSZ, chi, clo, bk, 1.0f, nullptr, khi, klo);
    hmma_gemm<1><<<dim3(Tv / 128, Cv / 128, Bv), 256, GEMM_SMEM_BYTES>>>(
        whi + 2 * WSZ, wlo + 2 * WSZ, chi, clo, bv, 1.0f, nullptr, vhi, vlo);

    // attention (writes split output into g_Xhi/g_Xlo)
    attn_hmma<<<dim3(Tv / 128, Hh, Bv), 256, ATTN_SMEM_BYTES>>>(ek, ev);

    // final projection (fp32 output)
    hmma_gemm<2><<<dim3(Tv / 128, Cv / 128, Bv), 256, GEMM_SMEM_BYTES>>>(
        whi + 3 * WSZ, wlo + 3 * WSZ, xhi, xlo, bo, 1.0f, out, nullptr, nullptr);
}